// round 5
// baseline (speedup 1.0000x reference)
#include <cuda_runtime.h>
#include <math.h>

#define NN 160000
#define EE 2560000
#define BB 16
#define VC 10000
#define KORD 6

// ---------------- static scratch (no allocations allowed) ----------------
__device__ float d_A[NN * 768];        // Chebyshev slabs, interleaved per row: A[n*Ktot + k*cin + c]
__device__ float d_OUT[NN * 128];      // per-layer conv output before GroupNorm
__device__ float d_H3[NN * 32];        // final layer activations
__device__ int   d_deg[NN];
__device__ float d_dis[NN];
__device__ int   d_rowptr[NN + 1];
__device__ int   d_cursor[NN];
__device__ int   d_colind[EE];
__device__ float d_val[EE];
__device__ int   d_blocksum[160];
__device__ float d_part[250 * 2048];   // final-GEMM split-K partials

static inline int cdiv(int a, int b) { return (a + b - 1) / b; }

// ---------------- graph preprocessing ----------------
__global__ void k_zero_deg() {
    int i = blockIdx.x * blockDim.x + threadIdx.x;
    if (i < NN) d_deg[i] = 0;
}

// edge_index is INT32: JAX x64 is disabled, astype(int64) yields int32.
__global__ void k_deg(const int* __restrict__ ei) {
    int e = blockIdx.x * blockDim.x + threadIdx.x;
    if (e < EE) atomicAdd(&d_deg[ei[e]], 1);
}

__global__ void k_dis() {
    int i = blockIdx.x * blockDim.x + threadIdx.x;
    if (i < NN) {
        int dg = d_deg[i];
        d_dis[i] = (dg > 0) ? rsqrtf((float)dg) : 0.0f;
    }
}

__global__ void k_scan1() {
    __shared__ int s[1024];
    int t = threadIdx.x;
    int idx = blockIdx.x * 1024 + t;
    int v = (idx < NN) ? d_deg[idx] : 0;
    s[t] = v;
    __syncthreads();
    for (int o = 1; o < 1024; o <<= 1) {
        int x = (t >= o) ? s[t - o] : 0;
        __syncthreads();
        s[t] += x;
        __syncthreads();
    }
    if (idx < NN) d_rowptr[idx] = s[t] - v;   // exclusive scan within block
    if (t == 1023) d_blocksum[blockIdx.x] = s[t];
}

__global__ void k_scan2(int nblk) {
    if (threadIdx.x == 0 && blockIdx.x == 0) {
        int run = 0;
        for (int i = 0; i < nblk; i++) {
            int u = d_blocksum[i];
            d_blocksum[i] = run;
            run += u;
        }
        d_rowptr[NN] = run;
    }
}

__global__ void k_scan3() {
    int i = blockIdx.x * blockDim.x + threadIdx.x;
    if (i < NN) {
        int r = d_rowptr[i] + d_blocksum[i >> 10];
        d_rowptr[i] = r;
        d_cursor[i] = r;
    }
}

__global__ void k_fill(const int* __restrict__ ei) {
    int e = blockIdx.x * blockDim.x + threadIdx.x;
    if (e < EE) {
        int r = ei[e];
        int c = ei[EE + e];
        int p = atomicAdd(&d_cursor[r], 1);
        d_colind[p] = c;
        d_val[p] = -d_dis[r] * d_dis[c];
    }
}

// ---------------- copy x into layer-0 slab 0 ----------------
__global__ void k_copy3(const float* __restrict__ x) {
    int i = blockIdx.x * blockDim.x + threadIdx.x;
    if (i < NN * 3) {
        int n = i / 3, c = i - n * 3;
        d_A[n * 18 + c] = x[i];
    }
}

// ---------------- Chebyshev propagation (SpMM) ----------------
// 128-thread blocks; blockDim.x = CIN channels, blockDim.y = 128/CIN rows.
template<int CIN>
__global__ void __launch_bounds__(128) k_prop(int inOff, int prevOff, int outOff,
                                              int stride, float alpha) {
    constexpr int ROWS = 128 / CIN;
    int n = blockIdx.x * ROWS + threadIdx.y;
    if (n >= NN) return;
    int c = threadIdx.x;
    int e0 = d_rowptr[n], e1 = d_rowptr[n + 1];
    const float* __restrict__ in = d_A + inOff;
    float acc = 0.0f;
    int e = e0;
    for (; e + 4 <= e1; e += 4) {
        int i0 = d_colind[e],     i1 = d_colind[e + 1];
        int i2 = d_colind[e + 2], i3 = d_colind[e + 3];
        float v0 = d_val[e],     v1 = d_val[e + 1];
        float v2 = d_val[e + 2], v3 = d_val[e + 3];
        float x0 = in[i0 * stride + c];
        float x1 = in[i1 * stride + c];
        float x2 = in[i2 * stride + c];
        float x3 = in[i3 * stride + c];
        acc = fmaf(v0, x0, acc);
        acc = fmaf(v1, x1, acc);
        acc = fmaf(v2, x2, acc);
        acc = fmaf(v3, x3, acc);
    }
    for (; e < e1; ++e)
        acc = fmaf(d_val[e], in[d_colind[e] * stride + c], acc);
    float r = alpha * acc;
    if (prevOff >= 0) r -= d_A[prevOff + n * stride + c];
    d_A[outOff + n * stride + c] = r;
}

// layer-0 prop: cin=3, one thread per row
__global__ void k_prop3(int inOff, int prevOff, int outOff, float alpha) {
    int n = blockIdx.x * blockDim.x + threadIdx.x;
    if (n >= NN) return;
    int e0 = d_rowptr[n], e1 = d_rowptr[n + 1];
    const float* __restrict__ in = d_A + inOff;
    float a0 = 0.f, a1 = 0.f, a2 = 0.f;
    for (int e = e0; e < e1; ++e) {
        int ci = d_colind[e];
        float v = d_val[e];
        const float* p = in + ci * 18;
        a0 = fmaf(v, p[0], a0);
        a1 = fmaf(v, p[1], a1);
        a2 = fmaf(v, p[2], a2);
    }
    int base = outOff + n * 18;
    if (prevOff >= 0) {
        int pb = prevOff + n * 18;
        d_A[base]     = alpha * a0 - d_A[pb];
        d_A[base + 1] = alpha * a1 - d_A[pb + 1];
        d_A[base + 2] = alpha * a2 - d_A[pb + 2];
    } else {
        d_A[base]     = alpha * a0;
        d_A[base + 1] = alpha * a1;
        d_A[base + 2] = alpha * a2;
    }
}

// ---------------- fp32 SGEMM: d_OUT[N,BN] = d_A[N,Ktot] @ W[Ktot,BN] + bias ----------------
template<int BN, int TN>
__global__ void __launch_bounds__(256) k_gemm(int Ktot,
                                              const float* __restrict__ W,
                                              const float* __restrict__ bias) {
    constexpr int BM = 128, BK = 16, TM = 8;
    __shared__ float As[BK][BM + 1];
    __shared__ float Ws[BK][BN];
    int tid = threadIdx.x;
    int tx = tid & 15, ty = tid >> 4;
    int rowBase = blockIdx.x * BM;

    float acc[TM][TN];
#pragma unroll
    for (int i = 0; i < TM; i++)
#pragma unroll
        for (int j = 0; j < TN; j++) acc[i][j] = 0.0f;

    for (int kk = 0; kk < Ktot; kk += BK) {
        // load A tile (consecutive tid -> consecutive k within a row)
#pragma unroll
        for (int it = 0; it < (BM * BK) / 256; it++) {
            int i = tid + it * 256;
            int r = i >> 4, k = i & 15;
            int kg = kk + k;
            As[k][r] = (kg < Ktot) ? d_A[(rowBase + r) * Ktot + kg] : 0.0f;
        }
        // load W tile
#pragma unroll
        for (int it = 0; it < (BK * BN) / 256; it++) {
            int i = tid + it * 256;
            int k = i / BN, col = i - k * BN;
            int kg = kk + k;
            Ws[k][col] = (kg < Ktot) ? W[kg * BN + col] : 0.0f;
        }
        __syncthreads();
#pragma unroll
        for (int kb = 0; kb < BK; kb++) {
            float a[TM], b[TN];
#pragma unroll
            for (int i = 0; i < TM; i++) a[i] = As[kb][ty * TM + i];
#pragma unroll
            for (int j = 0; j < TN; j++) b[j] = Ws[kb][tx * TN + j];
#pragma unroll
            for (int i = 0; i < TM; i++)
#pragma unroll
                for (int j = 0; j < TN; j++)
                    acc[i][j] = fmaf(a[i], b[j], acc[i][j]);
        }
        __syncthreads();
    }
#pragma unroll
    for (int i = 0; i < TM; i++) {
        int r = rowBase + ty * TM + i;
#pragma unroll
        for (int j = 0; j < TN; j++) {
            int col = tx * TN + j;
            d_OUT[r * BN + col] = acc[i][j] + bias[col];
        }
    }
}

// ---------------- GroupNorm + ReLU (warp-segment reduce), writes next layer's slab 0 ----------------
template<int C, int GS>
__global__ void k_gnorm(const float* __restrict__ gamma, const float* __restrict__ beta,
                        int dstStride, int toH3) {
    int idx = blockIdx.x * blockDim.x + threadIdx.x;
    if (idx >= NN * C) return;
    int row = idx / C, c = idx - row * C;
    float v = d_OUT[idx];
    float s = v, q = v * v;
#pragma unroll
    for (int o = GS / 2; o; o >>= 1) {
        s += __shfl_xor_sync(0xffffffffu, s, o);
        q += __shfl_xor_sync(0xffffffffu, q, o);
    }
    float mean = s * (1.0f / GS);
    float var = fmaxf(q * (1.0f / GS) - mean * mean, 0.0f);
    float y = (v - mean) * rsqrtf(var + 1e-5f);
    y = fmaxf(fmaf(y, gamma[c], beta[c]), 0.0f);
    if (toH3) d_H3[row * 32 + c] = y;
    else      d_A[row * dstStride + c] = y;
}

// ---------------- final projection: [16,320000] @ [320000,128], split-K ----------------
__global__ void __launch_bounds__(128) k_final(const float* __restrict__ Wl) {
    const int CHUNK = 1280;                 // 250 blocks * 1280 = 320000
    int blk = blockIdx.x;
    int t = threadIdx.x;                    // output column 0..127
    int j0base = blk * CHUNK;
    float acc[BB];
#pragma unroll
    for (int b = 0; b < BB; b++) acc[b] = 0.0f;
    __shared__ float Hs[BB][32];
    for (int jt = 0; jt < CHUNK; jt += 32) {
        int j0 = j0base + jt;
        for (int i = t; i < BB * 32; i += 128) {
            int b = i >> 5, jj = i & 31;
            Hs[b][jj] = d_H3[b * 320000 + j0 + jj];
        }
        __syncthreads();
#pragma unroll
        for (int jj = 0; jj < 32; jj++) {
            float w = Wl[(j0 + jj) * 128 + t];
#pragma unroll
            for (int b = 0; b < BB; b++)
                acc[b] = fmaf(Hs[b][jj], w, acc[b]);
        }
        __syncthreads();
    }
#pragma unroll
    for (int b = 0; b < BB; b++)
        d_part[blk * 2048 + b * 128 + t] = acc[b];
}

__global__ void k_reduce(const float* __restrict__ bl, float* __restrict__ out) {
    int o = blockIdx.x;     // 0..2047
    int t = threadIdx.x;    // 32 threads
    float s = 0.0f;
    for (int p = t; p < 250; p += 32) s += d_part[p * 2048 + o];
#pragma unroll
    for (int off = 16; off; off >>= 1)
        s += __shfl_down_sync(0xffffffffu, s, off);
    if (t == 0) out[o] = s + bl[o & 127];
}

// ---------------- launch ----------------
extern "C" void kernel_launch(void* const* d_in, const int* in_sizes, int n_in,
                              void* d_out, int out_size) {
    const float* x  = (const float*)d_in[0];
    const int*   ei = (const int*)d_in[1];          // int32! (JAX x64 disabled)
    const float* W0 = (const float*)d_in[2];
    const float* b0 = (const float*)d_in[3];
    const float* g0 = (const float*)d_in[4];
    const float* be0 = (const float*)d_in[5];
    const float* W1 = (const float*)d_in[6];
    const float* b1 = (const float*)d_in[7];
    const float* g1 = (const float*)d_in[8];
    const float* be1 = (const float*)d_in[9];
    const float* W2 = (const float*)d_in[10];
    const float* b2 = (const float*)d_in[11];
    const float* g2 = (const float*)d_in[12];
    const float* be2 = (const float*)d_in[13];
    const float* Wl = (const float*)d_in[14];
    const float* bl = (const float*)d_in[15];
    float* out = (float*)d_out;

    // --- graph preprocessing ---
    k_zero_deg<<<cdiv(NN, 256), 256>>>();
    k_deg<<<cdiv(EE, 256), 256>>>(ei);
    k_dis<<<cdiv(NN, 256), 256>>>();
    int nblk = cdiv(NN, 1024);
    k_scan1<<<nblk, 1024>>>();
    k_scan2<<<1, 32>>>(nblk);
    k_scan3<<<cdiv(NN, 256), 256>>>();
    k_fill<<<cdiv(EE, 256), 256>>>(ei);

    // --- layer 0: cin=3, cout=128, Ktot=18 ---
    k_copy3<<<cdiv(NN * 3, 256), 256>>>(x);
    k_prop3<<<cdiv(NN, 128), 128>>>(0, -1, 3, 1.0f);
    k_prop3<<<cdiv(NN, 128), 128>>>(3, 0, 6, 2.0f);
    k_prop3<<<cdiv(NN, 128), 128>>>(6, 3, 9, 2.0f);
    k_prop3<<<cdiv(NN, 128), 128>>>(9, 6, 12, 2.0f);
    k_prop3<<<cdiv(NN, 128), 128>>>(12, 9, 15, 2.0f);
    k_gemm<128, 8><<<NN / 128, 256>>>(18, W0, b0);
    k_gnorm<128, 16><<<cdiv(NN * 128, 256), 256>>>(g0, be0, 768, 0);

    // --- layer 1: cin=128, cout=64, Ktot=768, stride=768 ---
    {
        dim3 blk(128, 1);
        k_prop<128><<<NN, blk>>>(0,   -1,  128, 768, 1.0f);
        k_prop<128><<<NN, blk>>>(128,  0,  256, 768, 2.0f);
        k_prop<128><<<NN, blk>>>(256, 128, 384, 768, 2.0f);
        k_prop<128><<<NN, blk>>>(384, 256, 512, 768, 2.0f);
        k_prop<128><<<NN, blk>>>(512, 384, 640, 768, 2.0f);
    }
    k_gemm<64, 4><<<NN / 128, 256>>>(768, W1, b1);
    k_gnorm<64, 8><<<cdiv(NN * 64, 256), 256>>>(g1, be1, 384, 0);

    // --- layer 2: cin=64, cout=32, Ktot=384, stride=384 ---
    {
        dim3 blk(64, 2);                    // 2 rows per 128-thread block
        int g = cdiv(NN, 2);
        k_prop<64><<<g, blk>>>(0,   -1,  64, 384, 1.0f);
        k_prop<64><<<g, blk>>>(64,   0, 128, 384, 2.0f);
        k_prop<64><<<g, blk>>>(128, 64, 192, 384, 2.0f);
        k_prop<64><<<g, blk>>>(192, 128, 256, 384, 2.0f);
        k_prop<64><<<g, blk>>>(256, 192, 320, 384, 2.0f);
    }
    k_gemm<32, 2><<<NN / 128, 256>>>(384, W2, b2);
    k_gnorm<32, 4><<<cdiv(NN * 32, 256), 256>>>(g2, be2, 32, 1);

    // --- final projection ---
    k_final<<<250, 128>>>(Wl);
    k_reduce<<<2048, 32>>>(bl, out);
}

// round 6
// speedup vs baseline: 1.4310x; 1.4310x over previous
#include <cuda_runtime.h>
#include <math.h>

#define NN 160000
#define EE 2560000
#define BB 16

// ---- single big scratch arena (no allocations allowed) ----
// layout (floats):
#define OFF_A    0                    // NN*18  : layer0 Chebyshev slabs (interleaved k*3+c)
#define OFF_H    2880000              // NN*128 : post-GN activations (stride = layer C)
#define OFF_P    23360000             // NN*384 : P_k = H @ W_k slabs (stride 6*cout)
#define OFF_B0   84800000             // NN*64  : Clenshaw b buffers
#define OFF_B1   95040000
#define OFF_B2   105280000
#define OFF_OUT  115520000            // NN*128 : conv output pre-GroupNorm
#define OFF_H3   136000000            // NN*32  : final activations
__device__ float d_S[141120000];      // ~565 MB

__device__ int   d_deg[NN];
__device__ float d_dis[NN];
__device__ int   d_rowptr[NN + 1];
__device__ int   d_cursor[NN];
__device__ int   d_colind[EE];
__device__ float d_val[EE];
__device__ int   d_blocksum[160];
__device__ float d_part[250 * 2048];

static inline int cdiv(int a, int b) { return (a + b - 1) / b; }

// ---------------- graph preprocessing ----------------
__global__ void k_zero_deg() {
    int i = blockIdx.x * blockDim.x + threadIdx.x;
    if (i < NN) d_deg[i] = 0;
}

// edge_index is INT32 (JAX x64 disabled: astype(int64) yields int32)
__global__ void k_deg(const int* __restrict__ ei) {
    int e = blockIdx.x * blockDim.x + threadIdx.x;
    if (e < EE) atomicAdd(&d_deg[ei[e]], 1);
}

__global__ void k_dis() {
    int i = blockIdx.x * blockDim.x + threadIdx.x;
    if (i < NN) {
        int dg = d_deg[i];
        d_dis[i] = (dg > 0) ? rsqrtf((float)dg) : 0.0f;
    }
}

__global__ void k_scan1() {
    __shared__ int s[1024];
    int t = threadIdx.x;
    int idx = blockIdx.x * 1024 + t;
    int v = (idx < NN) ? d_deg[idx] : 0;
    s[t] = v;
    __syncthreads();
    for (int o = 1; o < 1024; o <<= 1) {
        int x = (t >= o) ? s[t - o] : 0;
        __syncthreads();
        s[t] += x;
        __syncthreads();
    }
    if (idx < NN) d_rowptr[idx] = s[t] - v;
    if (t == 1023) d_blocksum[blockIdx.x] = s[t];
}

__global__ void k_scan2(int nblk) {
    if (threadIdx.x == 0 && blockIdx.x == 0) {
        int run = 0;
        for (int i = 0; i < nblk; i++) {
            int u = d_blocksum[i];
            d_blocksum[i] = run;
            run += u;
        }
        d_rowptr[NN] = run;
    }
}

__global__ void k_scan3() {
    int i = blockIdx.x * blockDim.x + threadIdx.x;
    if (i < NN) {
        int r = d_rowptr[i] + d_blocksum[i >> 10];
        d_rowptr[i] = r;
        d_cursor[i] = r;
    }
}

__global__ void k_fill(const int* __restrict__ ei) {
    int e = blockIdx.x * blockDim.x + threadIdx.x;
    if (e < EE) {
        int r = ei[e];
        int c = ei[EE + e];
        int p = atomicAdd(&d_cursor[r], 1);
        d_colind[p] = c;
        d_val[p] = -d_dis[r] * d_dis[c];
    }
}

// ---------------- layer 0: copy x + standard Chebyshev recursion (cin=3) ----------------
__global__ void k_copy3(const float* __restrict__ x) {
    int i = blockIdx.x * blockDim.x + threadIdx.x;
    if (i < NN * 3) {
        int n = i / 3, c = i - n * 3;
        d_S[OFF_A + n * 18 + c] = x[i];
    }
}

__global__ void k_prop3(int inOff, int prevOff, int outOff, float alpha) {
    int n = blockIdx.x * blockDim.x + threadIdx.x;
    if (n >= NN) return;
    int e0 = d_rowptr[n], e1 = d_rowptr[n + 1];
    const float* __restrict__ in = d_S + OFF_A + inOff;
    float a0 = 0.f, a1 = 0.f, a2 = 0.f;
    for (int e = e0; e < e1; ++e) {
        int ci = d_colind[e];
        float v = d_val[e];
        const float* p = in + ci * 18;
        a0 = fmaf(v, p[0], a0);
        a1 = fmaf(v, p[1], a1);
        a2 = fmaf(v, p[2], a2);
    }
    int base = OFF_A + outOff + n * 18;
    if (prevOff >= 0) {
        int pb = OFF_A + prevOff + n * 18;
        d_S[base]     = alpha * a0 - d_S[pb];
        d_S[base + 1] = alpha * a1 - d_S[pb + 1];
        d_S[base + 2] = alpha * a2 - d_S[pb + 2];
    } else {
        d_S[base]     = alpha * a0;
        d_S[base + 1] = alpha * a1;
        d_S[base + 2] = alpha * a2;
    }
}

// ---------------- SGEMM: out[n, yblk*BN + col] = sum_k A[n,k] * W[(yblk*Ktot+k)*BN+col] ----------------
template<int BN, int TN>
__global__ void __launch_bounds__(256) k_gemm(int Ktot, int aOff, int aStride,
                                              int outOff, int outStride,
                                              const float* __restrict__ W,
                                              const float* __restrict__ bias) {
    constexpr int BM = 128, BK = 16, TM = 8;
    __shared__ float As[BK][BM + 1];
    __shared__ float Ws[BK][BN];
    int tid = threadIdx.x;
    int tx = tid & 15, ty = tid >> 4;
    int rowBase = blockIdx.x * BM;
    int wBase = blockIdx.y * Ktot;
    int colBase = blockIdx.y * BN;

    float acc[TM][TN];
#pragma unroll
    for (int i = 0; i < TM; i++)
#pragma unroll
        for (int j = 0; j < TN; j++) acc[i][j] = 0.0f;

    for (int kk = 0; kk < Ktot; kk += BK) {
#pragma unroll
        for (int it = 0; it < (BM * BK) / 256; it++) {
            int i = tid + it * 256;
            int r = i >> 4, k = i & 15;
            int kg = kk + k;
            As[k][r] = (kg < Ktot) ? d_S[aOff + (rowBase + r) * aStride + kg] : 0.0f;
        }
#pragma unroll
        for (int it = 0; it < (BK * BN) / 256; it++) {
            int i = tid + it * 256;
            int k = i / BN, col = i - k * BN;
            int kg = kk + k;
            Ws[k][col] = (kg < Ktot) ? W[(wBase + kg) * BN + col] : 0.0f;
        }
        __syncthreads();
#pragma unroll
        for (int kb = 0; kb < BK; kb++) {
            float a[TM], b[TN];
#pragma unroll
            for (int i = 0; i < TM; i++) a[i] = As[kb][ty * TM + i];
#pragma unroll
            for (int j = 0; j < TN; j++) b[j] = Ws[kb][tx * TN + j];
#pragma unroll
            for (int i = 0; i < TM; i++)
#pragma unroll
                for (int j = 0; j < TN; j++)
                    acc[i][j] = fmaf(a[i], b[j], acc[i][j]);
        }
        __syncthreads();
    }
#pragma unroll
    for (int i = 0; i < TM; i++) {
        int r = rowBase + ty * TM + i;
#pragma unroll
        for (int j = 0; j < TN; j++) {
            int col = tx * TN + j;
            float v = acc[i][j];
            if (bias) v += bias[colBase + col];
            d_S[outOff + r * outStride + colBase + col] = v;
        }
    }
}

// ---------------- Clenshaw propagation step, width W channels ----------------
// out[n,c] = alpha * sum_e val[e]*in[col[e],c]  + X[n,c]  (- prev[n,c])  (+ bias[c])
template<int W>
__global__ void __launch_bounds__(128) k_clenshaw(
    int inOff, int inS, int prevOff, int prevS,
    int xOff, int xS, int outOff, int outS,
    float alpha, const float* __restrict__ bias)
{
    constexpr int ROWS = 128 / W;
    int n = blockIdx.x * ROWS + threadIdx.y;
    if (n >= NN) return;
    int c = threadIdx.x;
    int e0 = d_rowptr[n], e1 = d_rowptr[n + 1];
    const float* __restrict__ in = d_S + inOff;
    float acc = 0.0f;
    int e = e0;
    for (; e + 4 <= e1; e += 4) {
        int i0 = d_colind[e],     i1 = d_colind[e + 1];
        int i2 = d_colind[e + 2], i3 = d_colind[e + 3];
        float v0 = d_val[e],     v1 = d_val[e + 1];
        float v2 = d_val[e + 2], v3 = d_val[e + 3];
        float x0 = in[i0 * inS + c];
        float x1 = in[i1 * inS + c];
        float x2 = in[i2 * inS + c];
        float x3 = in[i3 * inS + c];
        acc = fmaf(v0, x0, acc);
        acc = fmaf(v1, x1, acc);
        acc = fmaf(v2, x2, acc);
        acc = fmaf(v3, x3, acc);
    }
    for (; e < e1; ++e)
        acc = fmaf(d_val[e], in[d_colind[e] * inS + c], acc);

    float r = alpha * acc + d_S[xOff + n * xS + c];
    if (prevOff >= 0) r -= d_S[prevOff + n * prevS + c];
    if (bias) r += bias[c];
    d_S[outOff + n * outS + c] = r;
}

// ---------------- GroupNorm + ReLU (warp-segment reduce) ----------------
template<int C, int GS>
__global__ void k_gnorm(const float* __restrict__ gamma, const float* __restrict__ beta,
                        int srcOff, int dstOff) {
    int idx = blockIdx.x * blockDim.x + threadIdx.x;
    if (idx >= NN * C) return;
    int c = idx & (C - 1);
    float v = d_S[srcOff + idx];
    float s = v, q = v * v;
#pragma unroll
    for (int o = GS / 2; o; o >>= 1) {
        s += __shfl_xor_sync(0xffffffffu, s, o);
        q += __shfl_xor_sync(0xffffffffu, q, o);
    }
    float mean = s * (1.0f / GS);
    float var = fmaxf(q * (1.0f / GS) - mean * mean, 0.0f);
    float y = (v - mean) * rsqrtf(var + 1e-5f);
    y = fmaxf(fmaf(y, gamma[c], beta[c]), 0.0f);
    d_S[dstOff + idx] = y;
}

// ---------------- final projection: [16,320000] @ [320000,128], split-K ----------------
__global__ void __launch_bounds__(128) k_final(const float* __restrict__ Wl) {
    const int CHUNK = 1280;
    int blk = blockIdx.x;
    int t = threadIdx.x;
    int j0base = blk * CHUNK;
    float acc[BB];
#pragma unroll
    for (int b = 0; b < BB; b++) acc[b] = 0.0f;
    __shared__ float Hs[BB][32];
    for (int jt = 0; jt < CHUNK; jt += 32) {
        int j0 = j0base + jt;
        for (int i = t; i < BB * 32; i += 128) {
            int b = i >> 5, jj = i & 31;
            Hs[b][jj] = d_S[OFF_H3 + b * 320000 + j0 + jj];
        }
        __syncthreads();
#pragma unroll
        for (int jj = 0; jj < 32; jj++) {
            float w = Wl[(j0 + jj) * 128 + t];
#pragma unroll
            for (int b = 0; b < BB; b++)
                acc[b] = fmaf(Hs[b][jj], w, acc[b]);
        }
        __syncthreads();
    }
#pragma unroll
    for (int b = 0; b < BB; b++)
        d_part[blk * 2048 + b * 128 + t] = acc[b];
}

__global__ void k_reduce(const float* __restrict__ bl, float* __restrict__ out) {
    int o = blockIdx.x;
    int t = threadIdx.x;
    float s = 0.0f;
    for (int p = t; p < 250; p += 32) s += d_part[p * 2048 + o];
#pragma unroll
    for (int off = 16; off; off >>= 1)
        s += __shfl_down_sync(0xffffffffu, s, off);
    if (t == 0) out[o] = s + bl[o & 127];
}

// ---------------- launch ----------------
extern "C" void kernel_launch(void* const* d_in, const int* in_sizes, int n_in,
                              void* d_out, int out_size) {
    const float* x  = (const float*)d_in[0];
    const int*   ei = (const int*)d_in[1];          // int32 (JAX x64 disabled)
    const float* W0 = (const float*)d_in[2];
    const float* b0 = (const float*)d_in[3];
    const float* g0 = (const float*)d_in[4];
    const float* be0 = (const float*)d_in[5];
    const float* W1 = (const float*)d_in[6];
    const float* b1 = (const float*)d_in[7];
    const float* g1 = (const float*)d_in[8];
    const float* be1 = (const float*)d_in[9];
    const float* W2 = (const float*)d_in[10];
    const float* b2 = (const float*)d_in[11];
    const float* g2 = (const float*)d_in[12];
    const float* be2 = (const float*)d_in[13];
    const float* Wl = (const float*)d_in[14];
    const float* bl = (const float*)d_in[15];
    float* out = (float*)d_out;

    // --- graph preprocessing ---
    k_zero_deg<<<cdiv(NN, 256), 256>>>();
    k_deg<<<cdiv(EE, 256), 256>>>(ei);
    k_dis<<<cdiv(NN, 256), 256>>>();
    int nblk = cdiv(NN, 1024);
    k_scan1<<<nblk, 1024>>>();
    k_scan2<<<1, 32>>>(nblk);
    k_scan3<<<cdiv(NN, 256), 256>>>();
    k_fill<<<cdiv(EE, 256), 256>>>(ei);

    // --- layer 0: standard recursion (cin=3 -> cout=128), Ktot=18 ---
    k_copy3<<<cdiv(NN * 3, 256), 256>>>(x);
    k_prop3<<<cdiv(NN, 128), 128>>>(0, -1, 3, 1.0f);
    k_prop3<<<cdiv(NN, 128), 128>>>(3, 0, 6, 2.0f);
    k_prop3<<<cdiv(NN, 128), 128>>>(6, 3, 9, 2.0f);
    k_prop3<<<cdiv(NN, 128), 128>>>(9, 6, 12, 2.0f);
    k_prop3<<<cdiv(NN, 128), 128>>>(12, 9, 15, 2.0f);
    k_gemm<128, 8><<<dim3(NN / 128, 1), 256>>>(18, OFF_A, 18, OFF_OUT, 128, W0, b0);
    k_gnorm<128, 16><<<cdiv(NN * 128, 256), 256>>>(g0, be0, OFF_OUT, OFF_H);

    // --- layer 1 (cin=128 -> cout=64): P_k = H@W1_k, then Clenshaw (64-wide props) ---
    k_gemm<64, 4><<<dim3(NN / 128, 6), 256>>>(128, OFF_H, 128, OFF_P, 384, W1, (const float*)0);
    {
        const int P5 = OFF_P + 5 * 64, P4 = OFF_P + 4 * 64, P3 = OFF_P + 3 * 64;
        const int P2 = OFF_P + 2 * 64, P1 = OFF_P + 1 * 64, P0 = OFF_P;
        dim3 blk(64, 2); int g = NN / 2;
        // b4 = 2 L b5 + P4            (b5 = P5 slab, in-place in P)
        k_clenshaw<64><<<g, blk>>>(P5, 384, -1, 0, P4, 384, OFF_B0, 64, 2.0f, 0);
        // b3 = 2 L b4 - b5 + P3
        k_clenshaw<64><<<g, blk>>>(OFF_B0, 64, P5, 384, P3, 384, OFF_B1, 64, 2.0f, 0);
        // b2 = 2 L b3 - b4 + P2
        k_clenshaw<64><<<g, blk>>>(OFF_B1, 64, OFF_B0, 64, P2, 384, OFF_B2, 64, 2.0f, 0);
        // b1 = 2 L b2 - b3 + P1
        k_clenshaw<64><<<g, blk>>>(OFF_B2, 64, OFF_B1, 64, P1, 384, OFF_B0, 64, 2.0f, 0);
        // out = L b1 - b2 + P0 + bias
        k_clenshaw<64><<<g, blk>>>(OFF_B0, 64, OFF_B2, 64, P0, 384, OFF_OUT, 64, 1.0f, b1);
    }
    k_gnorm<64, 8><<<cdiv(NN * 64, 256), 256>>>(g1, be1, OFF_OUT, OFF_H);

    // --- layer 2 (cin=64 -> cout=32): Clenshaw (32-wide props) ---
    k_gemm<32, 2><<<dim3(NN / 128, 6), 256>>>(64, OFF_H, 64, OFF_P, 192, W2, (const float*)0);
    {
        const int P5 = OFF_P + 5 * 32, P4 = OFF_P + 4 * 32, P3 = OFF_P + 3 * 32;
        const int P2 = OFF_P + 2 * 32, P1 = OFF_P + 1 * 32, P0 = OFF_P;
        dim3 blk(32, 4); int g = NN / 4;
        k_clenshaw<32><<<g, blk>>>(P5, 192, -1, 0, P4, 192, OFF_B0, 32, 2.0f, 0);
        k_clenshaw<32><<<g, blk>>>(OFF_B0, 32, P5, 192, P3, 192, OFF_B1, 32, 2.0f, 0);
        k_clenshaw<32><<<g, blk>>>(OFF_B1, 32, OFF_B0, 32, P2, 192, OFF_B2, 32, 2.0f, 0);
        k_clenshaw<32><<<g, blk>>>(OFF_B2, 32, OFF_B1, 32, P1, 192, OFF_B0, 32, 2.0f, 0);
        k_clenshaw<32><<<g, blk>>>(OFF_B0, 32, OFF_B2, 32, P0, 192, OFF_OUT, 32, 1.0f, b2);
    }
    k_gnorm<32, 4><<<cdiv(NN * 32, 256), 256>>>(g2, be2, OFF_OUT, OFF_H3);

    // --- final projection ---
    k_final<<<250, 128>>>(Wl);
    k_reduce<<<2048, 32>>>(bl, out);
}

// round 7
// speedup vs baseline: 1.7989x; 1.2571x over previous
#include <cuda_runtime.h>
#include <math.h>

#define NN 160000
#define EE 2560000
#define BB 16

// ---- single big scratch arena (no allocations allowed) ----
#define OFF_A    0                    // NN*18  : layer0 Chebyshev slabs
#define OFF_H    2880000              // NN*128 : post-GN activations
#define OFF_P    23360000             // NN*384 : P_k = H @ W_k slabs
#define OFF_B0   84800000             // NN*64  : Clenshaw b buffers
#define OFF_B1   95040000
#define OFF_B2   105280000
#define OFF_OUT  115520000            // NN*128 : conv output pre-GroupNorm
#define OFF_H3   136000000            // NN*32  : final activations
__device__ float d_S[141120000];      // ~565 MB

__device__ int   d_deg[NN];
__device__ float d_dis[NN];
__device__ int   d_rowptr[NN + 1];
__device__ int   d_cursor[NN];
__device__ int   d_colind[EE];
__device__ float d_val[EE];
__device__ int   d_blocksum[160];
__device__ float d_part[250 * 2048];

static inline int cdiv(int a, int b) { return (a + b - 1) / b; }

// packed f32x2 helpers
__device__ __forceinline__ unsigned long long pack2(float x, float y) {
    unsigned long long r;
    asm("mov.b64 %0, {%1, %2};" : "=l"(r) : "r"(__float_as_uint(x)), "r"(__float_as_uint(y)));
    return r;
}
__device__ __forceinline__ void unpack2(unsigned long long p, float& x, float& y) {
    unsigned int lo, hi;
    asm("mov.b64 {%0, %1}, %2;" : "=r"(lo), "=r"(hi) : "l"(p));
    x = __uint_as_float(lo); y = __uint_as_float(hi);
}
__device__ __forceinline__ void ffma2(unsigned long long& d, unsigned long long a, unsigned long long b) {
    asm("fma.rn.f32x2 %0, %1, %2, %3;" : "=l"(d) : "l"(a), "l"(b), "l"(d));
}

// ---------------- graph preprocessing ----------------
__global__ void k_zero_deg() {
    int i = blockIdx.x * blockDim.x + threadIdx.x;
    if (i < NN) d_deg[i] = 0;
}

// edge_index is INT32 (JAX x64 disabled: astype(int64) yields int32)
__global__ void k_deg(const int* __restrict__ ei) {
    int e = blockIdx.x * blockDim.x + threadIdx.x;
    if (e < EE) atomicAdd(&d_deg[ei[e]], 1);
}

__global__ void k_dis() {
    int i = blockIdx.x * blockDim.x + threadIdx.x;
    if (i < NN) {
        int dg = d_deg[i];
        d_dis[i] = (dg > 0) ? rsqrtf((float)dg) : 0.0f;
    }
}

__global__ void k_scan1() {
    __shared__ int s[1024];
    int t = threadIdx.x;
    int idx = blockIdx.x * 1024 + t;
    int v = (idx < NN) ? d_deg[idx] : 0;
    s[t] = v;
    __syncthreads();
    for (int o = 1; o < 1024; o <<= 1) {
        int x = (t >= o) ? s[t - o] : 0;
        __syncthreads();
        s[t] += x;
        __syncthreads();
    }
    if (idx < NN) d_rowptr[idx] = s[t] - v;
    if (t == 1023) d_blocksum[blockIdx.x] = s[t];
}

__global__ void k_scan2(int nblk) {
    if (threadIdx.x == 0 && blockIdx.x == 0) {
        int run = 0;
        for (int i = 0; i < nblk; i++) {
            int u = d_blocksum[i];
            d_blocksum[i] = run;
            run += u;
        }
        d_rowptr[NN] = run;
    }
}

__global__ void k_scan3() {
    int i = blockIdx.x * blockDim.x + threadIdx.x;
    if (i < NN) {
        int r = d_rowptr[i] + d_blocksum[i >> 10];
        d_rowptr[i] = r;
        d_cursor[i] = r;
    }
}

__global__ void k_fill(const int* __restrict__ ei) {
    int e = blockIdx.x * blockDim.x + threadIdx.x;
    if (e < EE) {
        int r = ei[e];
        int c = ei[EE + e];
        int p = atomicAdd(&d_cursor[r], 1);
        d_colind[p] = c;
        d_val[p] = -d_dis[r] * d_dis[c];
    }
}

// ---------------- layer 0: copy x + standard Chebyshev recursion (cin=3) ----------------
__global__ void k_copy3(const float* __restrict__ x) {
    int i = blockIdx.x * blockDim.x + threadIdx.x;
    if (i < NN * 3) {
        int n = i / 3, c = i - n * 3;
        d_S[OFF_A + n * 18 + c] = x[i];
    }
}

__global__ void k_prop3(int inOff, int prevOff, int outOff, float alpha) {
    int n = blockIdx.x * blockDim.x + threadIdx.x;
    if (n >= NN) return;
    int e0 = d_rowptr[n], e1 = d_rowptr[n + 1];
    const float* __restrict__ in = d_S + OFF_A + inOff;
    float a0 = 0.f, a1 = 0.f, a2 = 0.f;
    for (int e = e0; e < e1; ++e) {
        int ci = d_colind[e];
        float v = d_val[e];
        const float* p = in + ci * 18;
        a0 = fmaf(v, p[0], a0);
        a1 = fmaf(v, p[1], a1);
        a2 = fmaf(v, p[2], a2);
    }
    int base = OFF_A + outOff + n * 18;
    if (prevOff >= 0) {
        int pb = OFF_A + prevOff + n * 18;
        d_S[base]     = alpha * a0 - d_S[pb];
        d_S[base + 1] = alpha * a1 - d_S[pb + 1];
        d_S[base + 2] = alpha * a2 - d_S[pb + 2];
    } else {
        d_S[base]     = alpha * a0;
        d_S[base + 1] = alpha * a1;
        d_S[base + 2] = alpha * a2;
    }
}

// ---------------- SGEMM with packed f32x2 FMA ----------------
// out[n, yblk*BN + col] = sum_k A[n,k] * W[(yblk*Ktot+k)*BN+col] (+bias)
template<int BN, int TN>
__global__ void __launch_bounds__(256) k_gemm(int Ktot, int aOff, int aStride,
                                              int outOff, int outStride,
                                              const float* __restrict__ W,
                                              const float* __restrict__ bias) {
    constexpr int BM = 128, BK = 16, TM = 8;
    __shared__ float As[BK][BM + 2];   // stride 130: float2-aligned rows, conflict-free stores
    __shared__ float Ws[BK][BN];
    int tid = threadIdx.x;
    int tx = tid & 15, ty = tid >> 4;
    int rowBase = blockIdx.x * BM;
    int wBase = blockIdx.y * Ktot;
    int colBase = blockIdx.y * BN;

    // acc2[i][j] packs output rows {2i, 2i+1} for column j
    unsigned long long acc2[TM / 2][TN];
#pragma unroll
    for (int i = 0; i < TM / 2; i++)
#pragma unroll
        for (int j = 0; j < TN; j++) acc2[i][j] = 0ull;

    for (int kk = 0; kk < Ktot; kk += BK) {
#pragma unroll
        for (int it = 0; it < (BM * BK) / 256; it++) {
            int i = tid + it * 256;
            int r = i >> 4, k = i & 15;
            int kg = kk + k;
            As[k][r] = (kg < Ktot) ? d_S[aOff + (rowBase + r) * aStride + kg] : 0.0f;
        }
#pragma unroll
        for (int it = 0; it < (BK * BN) / 256; it++) {
            int i = tid + it * 256;
            int k = i / BN, col = i - k * BN;
            int kg = kk + k;
            Ws[k][col] = (kg < Ktot) ? W[(wBase + kg) * BN + col] : 0.0f;
        }
        __syncthreads();
#pragma unroll
        for (int kb = 0; kb < BK; kb++) {
            unsigned long long a2[TM / 2], b2[TN];
            const float2* arow = reinterpret_cast<const float2*>(&As[kb][0]);
#pragma unroll
            for (int i = 0; i < TM / 2; i++) {
                float2 av = arow[ty * (TM / 2) + i];
                a2[i] = pack2(av.x, av.y);
            }
#pragma unroll
            for (int j = 0; j < TN; j++) {
                float bv = Ws[kb][tx * TN + j];
                b2[j] = pack2(bv, bv);
            }
#pragma unroll
            for (int i = 0; i < TM / 2; i++)
#pragma unroll
                for (int j = 0; j < TN; j++)
                    ffma2(acc2[i][j], a2[i], b2[j]);
        }
        __syncthreads();
    }
#pragma unroll
    for (int i = 0; i < TM / 2; i++) {
        int r0 = rowBase + ty * TM + 2 * i;
#pragma unroll
        for (int j = 0; j < TN; j++) {
            int col = tx * TN + j;
            float v0, v1;
            unpack2(acc2[i][j], v0, v1);
            if (bias) { float bv = bias[colBase + col]; v0 += bv; v1 += bv; }
            d_S[outOff + r0 * outStride + colBase + col] = v0;
            d_S[outOff + (r0 + 1) * outStride + colBase + col] = v1;
        }
    }
}

// ---------------- Clenshaw propagation step, width W channels, float2 per thread ----------------
// out[n,c] = alpha * sum_e val[e]*in[col[e],c] + X[n,c] (- prev[n,c]) (+ bias[c])
template<int W>
__global__ void __launch_bounds__(128) k_clenshaw(
    int inOff, int inS, int prevOff, int prevS,
    int xOff, int xS, int outOff, int outS,
    float alpha, const float* __restrict__ bias)
{
    constexpr int CP = W / 2;              // channel pairs per row
    constexpr int ROWS = 128 / CP;
    int n = blockIdx.x * ROWS + threadIdx.y;
    if (n >= NN) return;
    int c2 = threadIdx.x;                  // pair index
    int e0 = d_rowptr[n], e1 = d_rowptr[n + 1];
    const float2* __restrict__ in2 = reinterpret_cast<const float2*>(d_S + inOff);
    int inS2 = inS >> 1;
    float ax = 0.0f, ay = 0.0f;
    int e = e0;
    for (; e + 4 <= e1; e += 4) {
        int i0 = d_colind[e],     i1 = d_colind[e + 1];
        int i2 = d_colind[e + 2], i3 = d_colind[e + 3];
        float v0 = d_val[e],     v1 = d_val[e + 1];
        float v2 = d_val[e + 2], v3 = d_val[e + 3];
        float2 g0 = in2[i0 * inS2 + c2];
        float2 g1 = in2[i1 * inS2 + c2];
        float2 g2 = in2[i2 * inS2 + c2];
        float2 g3 = in2[i3 * inS2 + c2];
        ax = fmaf(v0, g0.x, ax); ay = fmaf(v0, g0.y, ay);
        ax = fmaf(v1, g1.x, ax); ay = fmaf(v1, g1.y, ay);
        ax = fmaf(v2, g2.x, ax); ay = fmaf(v2, g2.y, ay);
        ax = fmaf(v3, g3.x, ax); ay = fmaf(v3, g3.y, ay);
    }
    for (; e < e1; ++e) {
        float v = d_val[e];
        float2 g = in2[d_colind[e] * inS2 + c2];
        ax = fmaf(v, g.x, ax); ay = fmaf(v, g.y, ay);
    }

    const float2* x2 = reinterpret_cast<const float2*>(d_S + xOff);
    float2 xv = x2[n * (xS >> 1) + c2];
    float rx = fmaf(alpha, ax, xv.x);
    float ry = fmaf(alpha, ay, xv.y);
    if (prevOff >= 0) {
        const float2* p2 = reinterpret_cast<const float2*>(d_S + prevOff);
        float2 pv = p2[n * (prevS >> 1) + c2];
        rx -= pv.x; ry -= pv.y;
    }
    if (bias) {
        rx += bias[2 * c2];
        ry += bias[2 * c2 + 1];
    }
    float2* o2 = reinterpret_cast<float2*>(d_S + outOff);
    o2[n * (outS >> 1) + c2] = make_float2(rx, ry);
}

// ---------------- GroupNorm + ReLU (warp-segment reduce) ----------------
template<int C, int GS>
__global__ void k_gnorm(const float* __restrict__ gamma, const float* __restrict__ beta,
                        int srcOff, int dstOff) {
    int idx = blockIdx.x * blockDim.x + threadIdx.x;
    if (idx >= NN * C) return;
    int c = idx & (C - 1);
    float v = d_S[srcOff + idx];
    float s = v, q = v * v;
#pragma unroll
    for (int o = GS / 2; o; o >>= 1) {
        s += __shfl_xor_sync(0xffffffffu, s, o);
        q += __shfl_xor_sync(0xffffffffu, q, o);
    }
    float mean = s * (1.0f / GS);
    float var = fmaxf(q * (1.0f / GS) - mean * mean, 0.0f);
    float y = (v - mean) * rsqrtf(var + 1e-5f);
    y = fmaxf(fmaf(y, gamma[c], beta[c]), 0.0f);
    d_S[dstOff + idx] = y;
}

// ---------------- final projection: [16,320000] @ [320000,128], split-K ----------------
__global__ void __launch_bounds__(128) k_final(const float* __restrict__ Wl) {
    const int CHUNK = 1280;
    int blk = blockIdx.x;
    int t = threadIdx.x;
    int j0base = blk * CHUNK;
    float acc[BB];
#pragma unroll
    for (int b = 0; b < BB; b++) acc[b] = 0.0f;
    __shared__ float Hs[BB][32];
    for (int jt = 0; jt < CHUNK; jt += 32) {
        int j0 = j0base + jt;
        for (int i = t; i < BB * 32; i += 128) {
            int b = i >> 5, jj = i & 31;
            Hs[b][jj] = d_S[OFF_H3 + b * 320000 + j0 + jj];
        }
        __syncthreads();
#pragma unroll
        for (int jj = 0; jj < 32; jj++) {
            float w = Wl[(j0 + jj) * 128 + t];
#pragma unroll
            for (int b = 0; b < BB; b++)
                acc[b] = fmaf(Hs[b][jj], w, acc[b]);
        }
        __syncthreads();
    }
#pragma unroll
    for (int b = 0; b < BB; b++)
        d_part[blk * 2048 + b * 128 + t] = acc[b];
}

__global__ void k_reduce(const float* __restrict__ bl, float* __restrict__ out) {
    int o = blockIdx.x;
    int t = threadIdx.x;
    float s = 0.0f;
    for (int p = t; p < 250; p += 32) s += d_part[p * 2048 + o];
#pragma unroll
    for (int off = 16; off; off >>= 1)
        s += __shfl_down_sync(0xffffffffu, s, off);
    if (t == 0) out[o] = s + bl[o & 127];
}

// ---------------- launch ----------------
extern "C" void kernel_launch(void* const* d_in, const int* in_sizes, int n_in,
                              void* d_out, int out_size) {
    const float* x  = (const float*)d_in[0];
    const int*   ei = (const int*)d_in[1];          // int32 (JAX x64 disabled)
    const float* W0 = (const float*)d_in[2];
    const float* b0 = (const float*)d_in[3];
    const float* g0 = (const float*)d_in[4];
    const float* be0 = (const float*)d_in[5];
    const float* W1 = (const float*)d_in[6];
    const float* b1 = (const float*)d_in[7];
    const float* g1 = (const float*)d_in[8];
    const float* be1 = (const float*)d_in[9];
    const float* W2 = (const float*)d_in[10];
    const float* b2 = (const float*)d_in[11];
    const float* g2 = (const float*)d_in[12];
    const float* be2 = (const float*)d_in[13];
    const float* Wl = (const float*)d_in[14];
    const float* bl = (const float*)d_in[15];
    float* out = (float*)d_out;

    // --- graph preprocessing ---
    k_zero_deg<<<cdiv(NN, 256), 256>>>();
    k_deg<<<cdiv(EE, 256), 256>>>(ei);
    k_dis<<<cdiv(NN, 256), 256>>>();
    int nblk = cdiv(NN, 1024);
    k_scan1<<<nblk, 1024>>>();
    k_scan2<<<1, 32>>>(nblk);
    k_scan3<<<cdiv(NN, 256), 256>>>();
    k_fill<<<cdiv(EE, 256), 256>>>(ei);

    // --- layer 0: standard recursion (cin=3 -> cout=128), Ktot=18 ---
    k_copy3<<<cdiv(NN * 3, 256), 256>>>(x);
    k_prop3<<<cdiv(NN, 128), 128>>>(0, -1, 3, 1.0f);
    k_prop3<<<cdiv(NN, 128), 128>>>(3, 0, 6, 2.0f);
    k_prop3<<<cdiv(NN, 128), 128>>>(6, 3, 9, 2.0f);
    k_prop3<<<cdiv(NN, 128), 128>>>(9, 6, 12, 2.0f);
    k_prop3<<<cdiv(NN, 128), 128>>>(12, 9, 15, 2.0f);
    k_gemm<128, 8><<<dim3(NN / 128, 1), 256>>>(18, OFF_A, 18, OFF_OUT, 128, W0, b0);
    k_gnorm<128, 16><<<cdiv(NN * 128, 256), 256>>>(g0, be0, OFF_OUT, OFF_H);

    // --- layer 1 (cin=128 -> cout=64): P_k = H@W1_k, then Clenshaw (64-wide props) ---
    k_gemm<64, 4><<<dim3(NN / 128, 6), 256>>>(128, OFF_H, 128, OFF_P, 384, W1, (const float*)0);
    {
        const int P5 = OFF_P + 5 * 64, P4 = OFF_P + 4 * 64, P3 = OFF_P + 3 * 64;
        const int P2 = OFF_P + 2 * 64, P1 = OFF_P + 1 * 64, P0 = OFF_P;
        dim3 blk(32, 4); int g = NN / 4;   // float2: 32 pair-lanes per row, 4 rows/block
        k_clenshaw<64><<<g, blk>>>(P5, 384, -1, 0, P4, 384, OFF_B0, 64, 2.0f, 0);
        k_clenshaw<64><<<g, blk>>>(OFF_B0, 64, P5, 384, P3, 384, OFF_B1, 64, 2.0f, 0);
        k_clenshaw<64><<<g, blk>>>(OFF_B1, 64, OFF_B0, 64, P2, 384, OFF_B2, 64, 2.0f, 0);
        k_clenshaw<64><<<g, blk>>>(OFF_B2, 64, OFF_B1, 64, P1, 384, OFF_B0, 64, 2.0f, 0);
        k_clenshaw<64><<<g, blk>>>(OFF_B0, 64, OFF_B2, 64, P0, 384, OFF_OUT, 64, 1.0f, b1);
    }
    k_gnorm<64, 8><<<cdiv(NN * 64, 256), 256>>>(g1, be1, OFF_OUT, OFF_H);

    // --- layer 2 (cin=64 -> cout=32): Clenshaw (32-wide props) ---
    k_gemm<32, 2><<<dim3(NN / 128, 6), 256>>>(64, OFF_H, 64, OFF_P, 192, W2, (const float*)0);
    {
        const int P5 = OFF_P + 5 * 32, P4 = OFF_P + 4 * 32, P3 = OFF_P + 3 * 32;
        const int P2 = OFF_P + 2 * 32, P1 = OFF_P + 1 * 32, P0 = OFF_P;
        dim3 blk(16, 8); int g = NN / 8;   // float2: 16 pair-lanes per row, 8 rows/block
        k_clenshaw<32><<<g, blk>>>(P5, 192, -1, 0, P4, 192, OFF_B0, 32, 2.0f, 0);
        k_clenshaw<32><<<g, blk>>>(OFF_B0, 32, P5, 192, P3, 192, OFF_B1, 32, 2.0f, 0);
        k_clenshaw<32><<<g, blk>>>(OFF_B1, 32, OFF_B0, 32, P2, 192, OFF_B2, 32, 2.0f, 0);
        k_clenshaw<32><<<g, blk>>>(OFF_B2, 32, OFF_B1, 32, P1, 192, OFF_B0, 32, 2.0f, 0);
        k_clenshaw<32><<<g, blk>>>(OFF_B0, 32, OFF_B2, 32, P0, 192, OFF_OUT, 32, 1.0f, b2);
    }
    k_gnorm<32, 4><<<cdiv(NN * 32, 256), 256>>>(g2, be2, OFF_OUT, OFF_H3);

    // --- final projection ---
    k_final<<<250, 128>>>(Wl);
    k_reduce<<<2048, 32>>>(bl, out);
}

// round 8
// speedup vs baseline: 1.8829x; 1.0467x over previous
#include <cuda_runtime.h>
#include <cuda_fp16.h>
#include <math.h>

#define NN 160000
#define EE 2560000
#define BB 16

// ---- single big scratch arena (no allocations allowed) ----
#define OFF_A    0                    // NN*18  : layer0 Chebyshev slabs
#define OFF_H    2880000              // NN*128 : post-GN activations
#define OFF_P    23360000             // NN*384 : P_k = H @ W_k slabs
#define OFF_B0   84800000             // NN*64  : Clenshaw b buffers (fp32)
#define OFF_B1   95040000
#define OFF_B2   105280000
#define OFF_OUT  115520000            // NN*128 : conv output pre-GroupNorm
#define OFF_H3   136000000            // NN*32  : final activations
__device__ float d_S[141120000];      // ~565 MB

__device__ __half2 d_Bh0[NN * 32];    // half shadow of b (gather path), ping
__device__ __half2 d_Bh1[NN * 32];    // pong

__device__ int   d_deg[NN];
__device__ float d_dis[NN];
__device__ int   d_rowptr[NN + 1];
__device__ int   d_cursor[NN];
__device__ int   d_colind[EE];
__device__ float d_val[EE];
__device__ int   d_blocksum[160];
__device__ float d_part[1000 * 2048];

static inline int cdiv(int a, int b) { return (a + b - 1) / b; }

// packed f32x2 helpers
__device__ __forceinline__ unsigned long long pack2(float x, float y) {
    unsigned long long r;
    asm("mov.b64 %0, {%1, %2};" : "=l"(r) : "r"(__float_as_uint(x)), "r"(__float_as_uint(y)));
    return r;
}
__device__ __forceinline__ void unpack2(unsigned long long p, float& x, float& y) {
    unsigned int lo, hi;
    asm("mov.b64 {%0, %1}, %2;" : "=r"(lo), "=r"(hi) : "l"(p));
    x = __uint_as_float(lo); y = __uint_as_float(hi);
}
__device__ __forceinline__ void ffma2(unsigned long long& d, unsigned long long a, unsigned long long b) {
    asm("fma.rn.f32x2 %0, %1, %2, %3;" : "=l"(d) : "l"(a), "l"(b), "l"(d));
}

// ---------------- graph preprocessing ----------------
__global__ void k_zero_deg() {
    int i = blockIdx.x * blockDim.x + threadIdx.x;
    if (i < NN) d_deg[i] = 0;
}

// edge_index is INT32 (JAX x64 disabled: astype(int64) yields int32)
__global__ void k_deg(const int* __restrict__ ei) {
    int e = blockIdx.x * blockDim.x + threadIdx.x;
    if (e < EE) atomicAdd(&d_deg[ei[e]], 1);
}

__global__ void k_dis() {
    int i = blockIdx.x * blockDim.x + threadIdx.x;
    if (i < NN) {
        int dg = d_deg[i];
        d_dis[i] = (dg > 0) ? rsqrtf((float)dg) : 0.0f;
    }
}

__global__ void k_scan1() {
    __shared__ int s[1024];
    int t = threadIdx.x;
    int idx = blockIdx.x * 1024 + t;
    int v = (idx < NN) ? d_deg[idx] : 0;
    s[t] = v;
    __syncthreads();
    for (int o = 1; o < 1024; o <<= 1) {
        int x = (t >= o) ? s[t - o] : 0;
        __syncthreads();
        s[t] += x;
        __syncthreads();
    }
    if (idx < NN) d_rowptr[idx] = s[t] - v;
    if (t == 1023) d_blocksum[blockIdx.x] = s[t];
}

__global__ void k_scan2(int nblk) {
    if (threadIdx.x == 0 && blockIdx.x == 0) {
        int run = 0;
        for (int i = 0; i < nblk; i++) {
            int u = d_blocksum[i];
            d_blocksum[i] = run;
            run += u;
        }
        d_rowptr[NN] = run;
    }
}

__global__ void k_scan3() {
    int i = blockIdx.x * blockDim.x + threadIdx.x;
    if (i < NN) {
        int r = d_rowptr[i] + d_blocksum[i >> 10];
        d_rowptr[i] = r;
        d_cursor[i] = r;
    }
}

__global__ void k_fill(const int* __restrict__ ei) {
    int e = blockIdx.x * blockDim.x + threadIdx.x;
    if (e < EE) {
        int r = ei[e];
        int c = ei[EE + e];
        int p = atomicAdd(&d_cursor[r], 1);
        d_colind[p] = c;
        d_val[p] = -d_dis[r] * d_dis[c];
    }
}

// ---------------- layer 0: copy x + standard Chebyshev recursion (cin=3) ----------------
__global__ void k_copy3(const float* __restrict__ x) {
    int i = blockIdx.x * blockDim.x + threadIdx.x;
    if (i < NN * 3) {
        int n = i / 3, c = i - n * 3;
        d_S[OFF_A + n * 18 + c] = x[i];
    }
}

__global__ void k_prop3(int inOff, int prevOff, int outOff, float alpha) {
    int n = blockIdx.x * blockDim.x + threadIdx.x;
    if (n >= NN) return;
    int e0 = d_rowptr[n], e1 = d_rowptr[n + 1];
    const float* __restrict__ in = d_S + OFF_A + inOff;
    float a0 = 0.f, a1 = 0.f, a2 = 0.f;
    for (int e = e0; e < e1; ++e) {
        int ci = d_colind[e];
        float v = d_val[e];
        const float* p = in + ci * 18;
        a0 = fmaf(v, p[0], a0);
        a1 = fmaf(v, p[1], a1);
        a2 = fmaf(v, p[2], a2);
    }
    int base = OFF_A + outOff + n * 18;
    if (prevOff >= 0) {
        int pb = OFF_A + prevOff + n * 18;
        d_S[base]     = alpha * a0 - d_S[pb];
        d_S[base + 1] = alpha * a1 - d_S[pb + 1];
        d_S[base + 2] = alpha * a2 - d_S[pb + 2];
    } else {
        d_S[base]     = alpha * a0;
        d_S[base + 1] = alpha * a1;
        d_S[base + 2] = alpha * a2;
    }
}

// ---------------- SGEMM with packed f32x2 FMA ----------------
template<int BN, int TN>
__global__ void __launch_bounds__(256) k_gemm(int Ktot, int aOff, int aStride,
                                              int outOff, int outStride,
                                              const float* __restrict__ W,
                                              const float* __restrict__ bias) {
    constexpr int BM = 128, BK = 16, TM = 8;
    __shared__ float As[BK][BM + 2];   // stride 130: float2-aligned rows
    __shared__ float Ws[BK][BN];
    int tid = threadIdx.x;
    int tx = tid & 15, ty = tid >> 4;
    int rowBase = blockIdx.x * BM;
    int wBase = blockIdx.y * Ktot;
    int colBase = blockIdx.y * BN;

    unsigned long long acc2[TM / 2][TN];
#pragma unroll
    for (int i = 0; i < TM / 2; i++)
#pragma unroll
        for (int j = 0; j < TN; j++) acc2[i][j] = 0ull;

    for (int kk = 0; kk < Ktot; kk += BK) {
#pragma unroll
        for (int it = 0; it < (BM * BK) / 256; it++) {
            int i = tid + it * 256;
            int r = i >> 4, k = i & 15;
            int kg = kk + k;
            As[k][r] = (kg < Ktot) ? d_S[aOff + (rowBase + r) * aStride + kg] : 0.0f;
        }
#pragma unroll
        for (int it = 0; it < (BK * BN) / 256; it++) {
            int i = tid + it * 256;
            int k = i / BN, col = i - k * BN;
            int kg = kk + k;
            Ws[k][col] = (kg < Ktot) ? W[(wBase + kg) * BN + col] : 0.0f;
        }
        __syncthreads();
#pragma unroll
        for (int kb = 0; kb < BK; kb++) {
            unsigned long long a2[TM / 2], b2[TN];
            const float2* arow = reinterpret_cast<const float2*>(&As[kb][0]);
#pragma unroll
            for (int i = 0; i < TM / 2; i++) {
                float2 av = arow[ty * (TM / 2) + i];
                a2[i] = pack2(av.x, av.y);
            }
#pragma unroll
            for (int j = 0; j < TN; j++) {
                float bv = Ws[kb][tx * TN + j];
                b2[j] = pack2(bv, bv);
            }
#pragma unroll
            for (int i = 0; i < TM / 2; i++)
#pragma unroll
                for (int j = 0; j < TN; j++)
                    ffma2(acc2[i][j], a2[i], b2[j]);
        }
        __syncthreads();
    }
#pragma unroll
    for (int i = 0; i < TM / 2; i++) {
        int r0 = rowBase + ty * TM + 2 * i;
#pragma unroll
        for (int j = 0; j < TN; j++) {
            int col = tx * TN + j;
            float v0, v1;
            unpack2(acc2[i][j], v0, v1);
            if (bias) { float bv = bias[colBase + col]; v0 += bv; v1 += bv; }
            d_S[outOff + r0 * outStride + colBase + col] = v0;
            d_S[outOff + (r0 + 1) * outStride + colBase + col] = v1;
        }
    }
}

// ---------------- fp32 slab -> half2 shadow ----------------
// dst[n*(C/2)+c2] = half2(src[n*stride + 2c2], src[n*stride + 2c2+1])
__global__ void k_f2h(int srcOff, int srcStride, int Chalf, __half2* __restrict__ dst) {
    int idx = blockIdx.x * blockDim.x + threadIdx.x;
    if (idx >= NN * Chalf) return;
    int n = idx / Chalf, c2 = idx - n * Chalf;
    const float2* s2 = reinterpret_cast<const float2*>(d_S + srcOff);
    float2 v = s2[n * (srcStride >> 1) + c2];
    dst[idx] = __floats2half2_rn(v.x, v.y);
}

// ---------------- Clenshaw propagation, half2 gather path ----------------
// out[n,c] = alpha * sum_e val[e]*inH[col[e],c] + X[n,c] (- prev[n,c]) (+ bias[c])
// fp32 result written to d_S[outOff]; optionally half2 shadow to outH.
template<int W>
__global__ void __launch_bounds__(128) k_clenshaw(
    const __half2* __restrict__ inH,
    int prevOff, int prevS,
    int xOff, int xS, int outOff, int outS,
    __half2* __restrict__ outH,
    float alpha, const float* __restrict__ bias)
{
    constexpr int CP = W / 2;              // half2 lanes per row
    constexpr int ROWS = 128 / CP;
    int n = blockIdx.x * ROWS + threadIdx.y;
    if (n >= NN) return;
    int c2 = threadIdx.x;
    int e0 = d_rowptr[n], e1 = d_rowptr[n + 1];
    float ax = 0.0f, ay = 0.0f;
    int e = e0;
    for (; e + 4 <= e1; e += 4) {
        int i0 = d_colind[e],     i1 = d_colind[e + 1];
        int i2 = d_colind[e + 2], i3 = d_colind[e + 3];
        float v0 = d_val[e],     v1 = d_val[e + 1];
        float v2 = d_val[e + 2], v3 = d_val[e + 3];
        float2 g0 = __half22float2(inH[i0 * CP + c2]);
        float2 g1 = __half22float2(inH[i1 * CP + c2]);
        float2 g2 = __half22float2(inH[i2 * CP + c2]);
        float2 g3 = __half22float2(inH[i3 * CP + c2]);
        ax = fmaf(v0, g0.x, ax); ay = fmaf(v0, g0.y, ay);
        ax = fmaf(v1, g1.x, ax); ay = fmaf(v1, g1.y, ay);
        ax = fmaf(v2, g2.x, ax); ay = fmaf(v2, g2.y, ay);
        ax = fmaf(v3, g3.x, ax); ay = fmaf(v3, g3.y, ay);
    }
    for (; e < e1; ++e) {
        float v = d_val[e];
        float2 g = __half22float2(inH[d_colind[e] * CP + c2]);
        ax = fmaf(v, g.x, ax); ay = fmaf(v, g.y, ay);
    }

    const float2* x2 = reinterpret_cast<const float2*>(d_S + xOff);
    float2 xv = x2[n * (xS >> 1) + c2];
    float rx = fmaf(alpha, ax, xv.x);
    float ry = fmaf(alpha, ay, xv.y);
    if (prevOff >= 0) {
        const float2* p2 = reinterpret_cast<const float2*>(d_S + prevOff);
        float2 pv = p2[n * (prevS >> 1) + c2];
        rx -= pv.x; ry -= pv.y;
    }
    if (bias) {
        rx += bias[2 * c2];
        ry += bias[2 * c2 + 1];
    }
    float2* o2 = reinterpret_cast<float2*>(d_S + outOff);
    o2[n * (outS >> 1) + c2] = make_float2(rx, ry);
    if (outH) outH[n * CP + c2] = __floats2half2_rn(rx, ry);
}

// ---------------- GroupNorm + ReLU (warp-segment reduce) ----------------
template<int C, int GS>
__global__ void k_gnorm(const float* __restrict__ gamma, const float* __restrict__ beta,
                        int srcOff, int dstOff) {
    int idx = blockIdx.x * blockDim.x + threadIdx.x;
    if (idx >= NN * C) return;
    int c = idx & (C - 1);
    float v = d_S[srcOff + idx];
    float s = v, q = v * v;
#pragma unroll
    for (int o = GS / 2; o; o >>= 1) {
        s += __shfl_xor_sync(0xffffffffu, s, o);
        q += __shfl_xor_sync(0xffffffffu, q, o);
    }
    float mean = s * (1.0f / GS);
    float var = fmaxf(q * (1.0f / GS) - mean * mean, 0.0f);
    float y = (v - mean) * rsqrtf(var + 1e-5f);
    y = fmaxf(fmaf(y, gamma[c], beta[c]), 0.0f);
    d_S[dstOff + idx] = y;
}

// ---------------- final projection: [16,320000] @ [320000,128], split-K ----------------
__global__ void __launch_bounds__(128) k_final(const float* __restrict__ Wl) {
    const int CHUNK = 320;                  // 1000 blocks * 320 = 320000
    int blk = blockIdx.x;
    int t = threadIdx.x;
    int j0base = blk * CHUNK;
    float acc[BB];
#pragma unroll
    for (int b = 0; b < BB; b++) acc[b] = 0.0f;
    __shared__ float Hs[BB][32];
    for (int jt = 0; jt < CHUNK; jt += 32) {
        int j0 = j0base + jt;
        for (int i = t; i < BB * 32; i += 128) {
            int b = i >> 5, jj = i & 31;
            Hs[b][jj] = d_S[OFF_H3 + b * 320000 + j0 + jj];
        }
        __syncthreads();
#pragma unroll
        for (int jj = 0; jj < 32; jj++) {
            float w = Wl[(j0 + jj) * 128 + t];
#pragma unroll
            for (int b = 0; b < BB; b++)
                acc[b] = fmaf(Hs[b][jj], w, acc[b]);
        }
        __syncthreads();
    }
#pragma unroll
    for (int b = 0; b < BB; b++)
        d_part[blk * 2048 + b * 128 + t] = acc[b];
}

__global__ void k_reduce(const float* __restrict__ bl, float* __restrict__ out) {
    int o = blockIdx.x;
    int t = threadIdx.x;
    float s = 0.0f;
    for (int p = t; p < 1000; p += 32) s += d_part[p * 2048 + o];
#pragma unroll
    for (int off = 16; off; off >>= 1)
        s += __shfl_down_sync(0xffffffffu, s, off);
    if (t == 0) out[o] = s + bl[o & 127];
}

// ---------------- launch ----------------
extern "C" void kernel_launch(void* const* d_in, const int* in_sizes, int n_in,
                              void* d_out, int out_size) {
    const float* x  = (const float*)d_in[0];
    const int*   ei = (const int*)d_in[1];          // int32 (JAX x64 disabled)
    const float* W0 = (const float*)d_in[2];
    const float* b0 = (const float*)d_in[3];
    const float* g0 = (const float*)d_in[4];
    const float* be0 = (const float*)d_in[5];
    const float* W1 = (const float*)d_in[6];
    const float* b1 = (const float*)d_in[7];
    const float* g1 = (const float*)d_in[8];
    const float* be1 = (const float*)d_in[9];
    const float* W2 = (const float*)d_in[10];
    const float* b2 = (const float*)d_in[11];
    const float* g2 = (const float*)d_in[12];
    const float* be2 = (const float*)d_in[13];
    const float* Wl = (const float*)d_in[14];
    const float* bl = (const float*)d_in[15];
    float* out = (float*)d_out;

    __half2* H0; __half2* H1;
    cudaGetSymbolAddress((void**)&H0, d_Bh0);
    cudaGetSymbolAddress((void**)&H1, d_Bh1);

    // --- graph preprocessing ---
    k_zero_deg<<<cdiv(NN, 256), 256>>>();
    k_deg<<<cdiv(EE, 256), 256>>>(ei);
    k_dis<<<cdiv(NN, 256), 256>>>();
    int nblk = cdiv(NN, 1024);
    k_scan1<<<nblk, 1024>>>();
    k_scan2<<<1, 32>>>(nblk);
    k_scan3<<<cdiv(NN, 256), 256>>>();
    k_fill<<<cdiv(EE, 256), 256>>>(ei);

    // --- layer 0: standard recursion (cin=3 -> cout=128), Ktot=18 ---
    k_copy3<<<cdiv(NN * 3, 256), 256>>>(x);
    k_prop3<<<cdiv(NN, 128), 128>>>(0, -1, 3, 1.0f);
    k_prop3<<<cdiv(NN, 128), 128>>>(3, 0, 6, 2.0f);
    k_prop3<<<cdiv(NN, 128), 128>>>(6, 3, 9, 2.0f);
    k_prop3<<<cdiv(NN, 128), 128>>>(9, 6, 12, 2.0f);
    k_prop3<<<cdiv(NN, 128), 128>>>(12, 9, 15, 2.0f);
    k_gemm<128, 8><<<dim3(NN / 128, 1), 256>>>(18, OFF_A, 18, OFF_OUT, 128, W0, b0);
    k_gnorm<128, 16><<<cdiv(NN * 128, 256), 256>>>(g0, be0, OFF_OUT, OFF_H);

    // --- layer 1 (cin=128 -> cout=64): P_k = H@W1_k, then Clenshaw (half2 gathers) ---
    k_gemm<64, 4><<<dim3(NN / 128, 6), 256>>>(128, OFF_H, 128, OFF_P, 384, W1, (const float*)0);
    {
        const int P5 = OFF_P + 5 * 64, P4 = OFF_P + 4 * 64, P3 = OFF_P + 3 * 64;
        const int P2 = OFF_P + 2 * 64, P1 = OFF_P + 1 * 64, P0 = OFF_P;
        dim3 blk(32, 4); int g = NN / 4;
        k_f2h<<<cdiv(NN * 32, 256), 256>>>(P5, 384, 32, H0);       // b5 half shadow
        // b4 = 2 L b5 + P4
        k_clenshaw<64><<<g, blk>>>(H0, -1, 0, P4, 384, OFF_B0, 64, H1, 2.0f, 0);
        // b3 = 2 L b4 - b5 + P3
        k_clenshaw<64><<<g, blk>>>(H1, P5, 384, P3, 384, OFF_B1, 64, H0, 2.0f, 0);
        // b2 = 2 L b3 - b4 + P2
        k_clenshaw<64><<<g, blk>>>(H0, OFF_B0, 64, P2, 384, OFF_B2, 64, H1, 2.0f, 0);
        // b1 = 2 L b2 - b3 + P1
        k_clenshaw<64><<<g, blk>>>(H1, OFF_B1, 64, P1, 384, OFF_B0, 64, H0, 2.0f, 0);
        // out = L b1 - b2 + P0 + bias
        k_clenshaw<64><<<g, blk>>>(H0, OFF_B2, 64, P0, 384, OFF_OUT, 64, (__half2*)0, 1.0f, b1);
    }
    k_gnorm<64, 8><<<cdiv(NN * 64, 256), 256>>>(g1, be1, OFF_OUT, OFF_H);

    // --- layer 2 (cin=64 -> cout=32): Clenshaw (half2 gathers) ---
    k_gemm<32, 2><<<dim3(NN / 128, 6), 256>>>(64, OFF_H, 64, OFF_P, 192, W2, (const float*)0);
    {
        const int P5 = OFF_P + 5 * 32, P4 = OFF_P + 4 * 32, P3 = OFF_P + 3 * 32;
        const int P2 = OFF_P + 2 * 32, P1 = OFF_P + 1 * 32, P0 = OFF_P;
        dim3 blk(16, 8); int g = NN / 8;
        k_f2h<<<cdiv(NN * 16, 256), 256>>>(P5, 192, 16, H0);
        k_clenshaw<32><<<g, blk>>>(H0, -1, 0, P4, 192, OFF_B0, 32, H1, 2.0f, 0);
        k_clenshaw<32><<<g, blk>>>(H1, P5, 192, P3, 192, OFF_B1, 32, H0, 2.0f, 0);
        k_clenshaw<32><<<g, blk>>>(H0, OFF_B0, 32, P2, 192, OFF_B2, 32, H1, 2.0f, 0);
        k_clenshaw<32><<<g, blk>>>(H1, OFF_B1, 32, P1, 192, OFF_B0, 32, H0, 2.0f, 0);
        k_clenshaw<32><<<g, blk>>>(H0, OFF_B2, 32, P0, 192, OFF_OUT, 32, (__half2*)0, 1.0f, b2);
    }
    k_gnorm<32, 4><<<cdiv(NN * 32, 256), 256>>>(g2, be2, OFF_OUT, OFF_H3);

    // --- final projection ---
    k_final<<<1000, 128>>>(Wl);
    k_reduce<<<2048, 32>>>(bl, out);
}

// round 10
// speedup vs baseline: 1.9729x; 1.0478x over previous
#include <cuda_runtime.h>
#include <cuda_fp16.h>
#include <math.h>

#define NN 160000
#define EE 2560000
#define BB 16

// ---- scratch arena layout (floats) ----
#define OFF_A4   0                    // 6 slabs * NN float4 : layer0 Cheb slabs
#define OFF_A18  3840000              // NN*18 : packed layer0 slabs for GEMM
#define OFF_P    6720000              // NN*384 : P_k = H @ W_k slabs
#define OFF_B0   68160000             // NN*64 : Clenshaw b buffers (fp32)
#define OFF_B1   78400000
#define OFF_B2   88640000
#define OFF_OUT  98880000             // NN*128 : conv output pre-GroupNorm
#define OFF_H3   119360000            // NN*32 : final activations
__device__ float d_S[124480000];      // ~498 MB

__device__ __half d_Hh[NN * 128];     // fp16 hi of post-GN activations (GEMM A)
__device__ __half d_Hr[NN * 128];     // fp16 residual of A
#define WT_TOT (6 * 64 * 128 + 6 * 32 * 64)
__device__ __half d_Wth[WT_TOT];      // transposed fp16 hi weights
__device__ __half d_Wtr[WT_TOT];      // transposed fp16 residual weights
#define WT2_OFF (6 * 64 * 128)

__device__ __half2 d_Bh0[NN * 32];    // half shadow of b (gather path), ping
__device__ __half2 d_Bh1[NN * 32];    // pong

__device__ int   d_deg[NN];
__device__ float d_dis[NN];
__device__ int   d_rowptr[NN + 1];
__device__ int   d_cursor[NN];
__device__ int   d_colind[EE];
__device__ float d_val[EE];
__device__ int   d_blocksum[160];
__device__ float d_part[1000 * 2048];

static inline int cdiv(int a, int b) { return (a + b - 1) / b; }

// packed f32x2 helpers (L0 SGEMM)
__device__ __forceinline__ unsigned long long pack2(float x, float y) {
    unsigned long long r;
    asm("mov.b64 %0, {%1, %2};" : "=l"(r) : "r"(__float_as_uint(x)), "r"(__float_as_uint(y)));
    return r;
}
__device__ __forceinline__ void unpack2(unsigned long long p, float& x, float& y) {
    unsigned int lo, hi;
    asm("mov.b64 {%0, %1}, %2;" : "=r"(lo), "=r"(hi) : "l"(p));
    x = __uint_as_float(lo); y = __uint_as_float(hi);
}
__device__ __forceinline__ void ffma2(unsigned long long& d, unsigned long long a, unsigned long long b) {
    asm("fma.rn.f32x2 %0, %1, %2, %3;" : "=l"(d) : "l"(a), "l"(b), "l"(d));
}

__device__ __forceinline__ void mma_f16(float* acc, const unsigned* a, unsigned b0, unsigned b1) {
    asm volatile(
        "mma.sync.aligned.m16n8k16.row.col.f32.f16.f16.f32 "
        "{%0,%1,%2,%3}, {%4,%5,%6,%7}, {%8,%9}, {%0,%1,%2,%3};"
        : "+f"(acc[0]), "+f"(acc[1]), "+f"(acc[2]), "+f"(acc[3])
        : "r"(a[0]), "r"(a[1]), "r"(a[2]), "r"(a[3]), "r"(b0), "r"(b1));
}

// ---------------- graph preprocessing ----------------
__global__ void k_zero_deg() {
    int i = blockIdx.x * blockDim.x + threadIdx.x;
    if (i < NN) d_deg[i] = 0;
}
__global__ void k_deg(const int* __restrict__ ei) {
    int e = blockIdx.x * blockDim.x + threadIdx.x;
    if (e < EE) atomicAdd(&d_deg[ei[e]], 1);
}
__global__ void k_dis() {
    int i = blockIdx.x * blockDim.x + threadIdx.x;
    if (i < NN) {
        int dg = d_deg[i];
        d_dis[i] = (dg > 0) ? rsqrtf((float)dg) : 0.0f;
    }
}
__global__ void k_scan1() {
    __shared__ int s[1024];
    int t = threadIdx.x;
    int idx = blockIdx.x * 1024 + t;
    int v = (idx < NN) ? d_deg[idx] : 0;
    s[t] = v;
    __syncthreads();
    for (int o = 1; o < 1024; o <<= 1) {
        int x = (t >= o) ? s[t - o] : 0;
        __syncthreads();
        s[t] += x;
        __syncthreads();
    }
    if (idx < NN) d_rowptr[idx] = s[t] - v;
    if (t == 1023) d_blocksum[blockIdx.x] = s[t];
}
__global__ void k_scan2(int nblk) {
    if (threadIdx.x == 0 && blockIdx.x == 0) {
        int run = 0;
        for (int i = 0; i < nblk; i++) {
            int u = d_blocksum[i];
            d_blocksum[i] = run;
            run += u;
        }
        d_rowptr[NN] = run;
    }
}
__global__ void k_scan3() {
    int i = blockIdx.x * blockDim.x + threadIdx.x;
    if (i < NN) {
        int r = d_rowptr[i] + d_blocksum[i >> 10];
        d_rowptr[i] = r;
        d_cursor[i] = r;
    }
}
__global__ void k_fill(const int* __restrict__ ei) {
    int e = blockIdx.x * blockDim.x + threadIdx.x;
    if (e < EE) {
        int r = ei[e];
        int c = ei[EE + e];
        int p = atomicAdd(&d_cursor[r], 1);
        d_colind[p] = c;
        d_val[p] = -d_dis[r] * d_dis[c];
    }
}

// ---------------- weight convert+transpose (hi + residual) ----------------
// out[(k*COUT+c)*CIN+j] = fp16split(W[(k*CIN+j)*COUT+c])
__global__ void k_wconv(const float* __restrict__ W, int CIN, int COUT,
                        __half* __restrict__ oh, __half* __restrict__ orr) {
    int idx = blockIdx.x * blockDim.x + threadIdx.x;
    int tot = 6 * CIN * COUT;
    if (idx >= tot) return;
    int k = idx / (CIN * COUT);
    int rem = idx - k * (CIN * COUT);
    int c = rem / CIN;
    int j = rem - c * CIN;
    float v = W[(k * CIN + j) * COUT + c];
    __half h = __float2half_rn(v);
    oh[(k * COUT + c) * CIN + j] = h;
    orr[(k * COUT + c) * CIN + j] = __float2half_rn(v - __half2float(h));
}

// ---------------- layer 0: copy x + standard Chebyshev recursion (cin=3, float4 slabs) ----------------
__global__ void k_copy3(const float* __restrict__ x) {
    int n = blockIdx.x * blockDim.x + threadIdx.x;
    if (n >= NN) return;
    float a = x[3 * n], b = x[3 * n + 1], c = x[3 * n + 2];
    float4* A4 = reinterpret_cast<float4*>(d_S + OFF_A4);
    A4[n] = make_float4(a, b, c, 0.0f);
    float* pk = d_S + OFF_A18 + n * 18;
    pk[0] = a; pk[1] = b; pk[2] = c;
}

__global__ void k_prop3(int si, int sp, int so, float alpha) {
    int n = blockIdx.x * blockDim.x + threadIdx.x;
    if (n >= NN) return;
    int e0 = d_rowptr[n], e1 = d_rowptr[n + 1];
    float4* A4 = reinterpret_cast<float4*>(d_S + OFF_A4);
    const float4* __restrict__ in = A4 + (size_t)si * NN;
    float a0 = 0.f, a1 = 0.f, a2 = 0.f;
    for (int e = e0; e < e1; ++e) {
        int ci = d_colind[e];
        float v = d_val[e];
        float4 q = __ldg(in + ci);
        a0 = fmaf(v, q.x, a0);
        a1 = fmaf(v, q.y, a1);
        a2 = fmaf(v, q.z, a2);
    }
    float rx = alpha * a0, ry = alpha * a1, rz = alpha * a2;
    if (sp >= 0) {
        float4 pv = A4[(size_t)sp * NN + n];
        rx -= pv.x; ry -= pv.y; rz -= pv.z;
    }
    A4[(size_t)so * NN + n] = make_float4(rx, ry, rz, 0.0f);
    float* pk = d_S + OFF_A18 + n * 18 + so * 3;
    pk[0] = rx; pk[1] = ry; pk[2] = rz;
}

// ---------------- L0 SGEMM (fp32 FFMA2): d_OUT[N,128] = A18[N,18] @ W0[18,128] + b0 ----------------
template<int BN, int TN>
__global__ void __launch_bounds__(256) k_gemm(int Ktot, int aOff, int aStride,
                                              int outOff, int outStride,
                                              const float* __restrict__ W,
                                              const float* __restrict__ bias) {
    constexpr int BM = 128, BK = 16, TM = 8;
    __shared__ float As[BK][BM + 2];
    __shared__ float Ws[BK][BN];
    int tid = threadIdx.x;
    int tx = tid & 15, ty = tid >> 4;
    int rowBase = blockIdx.x * BM;

    unsigned long long acc2[TM / 2][TN];
#pragma unroll
    for (int i = 0; i < TM / 2; i++)
#pragma unroll
        for (int j = 0; j < TN; j++) acc2[i][j] = 0ull;

    for (int kk = 0; kk < Ktot; kk += BK) {
#pragma unroll
        for (int it = 0; it < (BM * BK) / 256; it++) {
            int i = tid + it * 256;
            int r = i >> 4, k = i & 15;
            int kg = kk + k;
            As[k][r] = (kg < Ktot) ? d_S[aOff + (rowBase + r) * aStride + kg] : 0.0f;
        }
#pragma unroll
        for (int it = 0; it < (BK * BN) / 256; it++) {
            int i = tid + it * 256;
            int k = i / BN, col = i - k * BN;
            int kg = kk + k;
            Ws[k][col] = (kg < Ktot) ? W[kg * BN + col] : 0.0f;
        }
        __syncthreads();
#pragma unroll
        for (int kb = 0; kb < BK; kb++) {
            unsigned long long a2[TM / 2], b2[TN];
            const float2* arow = reinterpret_cast<const float2*>(&As[kb][0]);
#pragma unroll
            for (int i = 0; i < TM / 2; i++) {
                float2 av = arow[ty * (TM / 2) + i];
                a2[i] = pack2(av.x, av.y);
            }
#pragma unroll
            for (int j = 0; j < TN; j++) {
                float bv = Ws[kb][tx * TN + j];
                b2[j] = pack2(bv, bv);
            }
#pragma unroll
            for (int i = 0; i < TM / 2; i++)
#pragma unroll
                for (int j = 0; j < TN; j++)
                    ffma2(acc2[i][j], a2[i], b2[j]);
        }
        __syncthreads();
    }
#pragma unroll
    for (int i = 0; i < TM / 2; i++) {
        int r0 = rowBase + ty * TM + 2 * i;
#pragma unroll
        for (int j = 0; j < TN; j++) {
            int col = tx * TN + j;
            float v0, v1;
            unpack2(acc2[i][j], v0, v1);
            if (bias) { float bv = bias[col]; v0 += bv; v1 += bv; }
            d_S[outOff + r0 * outStride + col] = v0;
            d_S[outOff + (r0 + 1) * outStride + col] = v1;
        }
    }
}

// ---------------- split-fp16 HMMA GEMM: P = (Ah+Ar) @ (Wh+Wr)^T, fp32 accurate ----------------
// D = Ah*Wh + Ah*Wr + Ar*Wh  (Ar*Wr dropped, O(eps^2))
// A [NN x KTOT] fp16 row-major gmem; W slab [BN x KTOT] fp16 in smem.
// grid (NN/128, 6), 256 thr = 8 warps (4M x 2N), warp tile 32 x BN/2.
template<int KTOT, int BN>
__global__ void __launch_bounds__(256) k_hgemm(const __half* __restrict__ Ah,
                                               const __half* __restrict__ Ar,
                                               const __half* __restrict__ Wh,
                                               const __half* __restrict__ Wr,
                                               int outOff) {
    constexpr int NT = BN / 16;          // n8 tiles per warp
    constexpr int SROW = KTOT + 8;
    __shared__ __half sBh[BN * SROW];
    __shared__ __half sBr[BN * SROW];
    int tid = threadIdx.x;
    int warp = tid >> 5, lane = tid & 31;
    int g = lane >> 2, t = lane & 3;
    int wm = warp >> 1, wn = warp & 1;
    int rowBase = blockIdx.x * 128;
    int slab = blockIdx.y;

    const __half* whs = Wh + slab * BN * KTOT;
    const __half* wrs = Wr + slab * BN * KTOT;
    for (int i = tid; i < BN * KTOT; i += 256) {
        int r = i / KTOT, c = i - r * KTOT;
        sBh[r * SROW + c] = whs[i];
        sBr[r * SROW + c] = wrs[i];
    }
    __syncthreads();

    float acc[2][NT][4];
#pragma unroll
    for (int mt = 0; mt < 2; mt++)
#pragma unroll
        for (int nt = 0; nt < NT; nt++)
#pragma unroll
            for (int q = 0; q < 4; q++) acc[mt][nt][q] = 0.0f;

    size_t aRow = (size_t)(rowBase + wm * 32 + g) * KTOT;

#pragma unroll
    for (int k16 = 0; k16 < KTOT; k16 += 16) {
        unsigned aH[2][4], aR[2][4];
#pragma unroll
        for (int mt = 0; mt < 2; mt++) {
            size_t base = aRow + (size_t)mt * 16 * KTOT + k16 + 2 * t;
            aH[mt][0] = *reinterpret_cast<const unsigned*>(Ah + base);
            aH[mt][1] = *reinterpret_cast<const unsigned*>(Ah + base + 8 * KTOT);
            aH[mt][2] = *reinterpret_cast<const unsigned*>(Ah + base + 8);
            aH[mt][3] = *reinterpret_cast<const unsigned*>(Ah + base + 8 * KTOT + 8);
            aR[mt][0] = *reinterpret_cast<const unsigned*>(Ar + base);
            aR[mt][1] = *reinterpret_cast<const unsigned*>(Ar + base + 8 * KTOT);
            aR[mt][2] = *reinterpret_cast<const unsigned*>(Ar + base + 8);
            aR[mt][3] = *reinterpret_cast<const unsigned*>(Ar + base + 8 * KTOT + 8);
        }
#pragma unroll
        for (int nt = 0; nt < NT; nt++) {
            int ncol = wn * (BN / 2) + nt * 8 + g;
            const __half* bph = sBh + ncol * SROW + k16 + 2 * t;
            const __half* bpr = sBr + ncol * SROW + k16 + 2 * t;
            unsigned bh0 = *reinterpret_cast<const unsigned*>(bph);
            unsigned bh1 = *reinterpret_cast<const unsigned*>(bph + 8);
            unsigned br0 = *reinterpret_cast<const unsigned*>(bpr);
            unsigned br1 = *reinterpret_cast<const unsigned*>(bpr + 8);
#pragma unroll
            for (int mt = 0; mt < 2; mt++) {
                mma_f16(acc[mt][nt], aH[mt], bh0, bh1);
                mma_f16(acc[mt][nt], aH[mt], br0, br1);
                mma_f16(acc[mt][nt], aR[mt], bh0, bh1);
            }
        }
    }

    const int outStride = 6 * BN;
#pragma unroll
    for (int mt = 0; mt < 2; mt++) {
        int r0 = rowBase + wm * 32 + mt * 16 + g;
#pragma unroll
        for (int nt = 0; nt < NT; nt++) {
            int col = slab * BN + wn * (BN / 2) + nt * 8 + 2 * t;
            *reinterpret_cast<float2*>(d_S + outOff + (size_t)r0 * outStride + col) =
                make_float2(acc[mt][nt][0], acc[mt][nt][1]);
            *reinterpret_cast<float2*>(d_S + outOff + (size_t)(r0 + 8) * outStride + col) =
                make_float2(acc[mt][nt][2], acc[mt][nt][3]);
        }
    }
}

// ---------------- fp32 slab -> half2 shadow ----------------
__global__ void k_f2h(int srcOff, int srcStride, int Chalf, __half2* __restrict__ dst) {
    int idx = blockIdx.x * blockDim.x + threadIdx.x;
    if (idx >= NN * Chalf) return;
    int n = idx / Chalf, c2 = idx - n * Chalf;
    const float2* s2 = reinterpret_cast<const float2*>(d_S + srcOff);
    float2 v = s2[n * (srcStride >> 1) + c2];
    dst[idx] = __floats2half2_rn(v.x, v.y);
}

// ---------------- Clenshaw propagation, half2 gather path ----------------
template<int W>
__global__ void __launch_bounds__(128) k_clenshaw(
    const __half2* __restrict__ inH,
    int prevOff, int prevS,
    int xOff, int xS, int outOff, int outS,
    __half2* __restrict__ outH,
    float alpha, const float* __restrict__ bias)
{
    constexpr int CP = W / 2;
    constexpr int ROWS = 128 / CP;
    int n = blockIdx.x * ROWS + threadIdx.y;
    if (n >= NN) return;
    int c2 = threadIdx.x;
    int e0 = d_rowptr[n], e1 = d_rowptr[n + 1];
    float ax = 0.0f, ay = 0.0f;
    int e = e0;
    for (; e + 4 <= e1; e += 4) {
        int i0 = d_colind[e],     i1 = d_colind[e + 1];
        int i2 = d_colind[e + 2], i3 = d_colind[e + 3];
        float v0 = d_val[e],     v1 = d_val[e + 1];
        float v2 = d_val[e + 2], v3 = d_val[e + 3];
        float2 g0 = __half22float2(inH[i0 * CP + c2]);
        float2 g1 = __half22float2(inH[i1 * CP + c2]);
        float2 g2 = __half22float2(inH[i2 * CP + c2]);
        float2 g3 = __half22float2(inH[i3 * CP + c2]);
        ax = fmaf(v0, g0.x, ax); ay = fmaf(v0, g0.y, ay);
        ax = fmaf(v1, g1.x, ax); ay = fmaf(v1, g1.y, ay);
        ax = fmaf(v2, g2.x, ax); ay = fmaf(v2, g2.y, ay);
        ax = fmaf(v3, g3.x, ax); ay = fmaf(v3, g3.y, ay);
    }
    for (; e < e1; ++e) {
        float v = d_val[e];
        float2 gq = __half22float2(inH[d_colind[e] * CP + c2]);
        ax = fmaf(v, gq.x, ax); ay = fmaf(v, gq.y, ay);
    }

    const float2* x2 = reinterpret_cast<const float2*>(d_S + xOff);
    float2 xv = x2[n * (xS >> 1) + c2];
    float rx = fmaf(alpha, ax, xv.x);
    float ry = fmaf(alpha, ay, xv.y);
    if (prevOff >= 0) {
        const float2* p2 = reinterpret_cast<const float2*>(d_S + prevOff);
        float2 pv = p2[n * (prevS >> 1) + c2];
        rx -= pv.x; ry -= pv.y;
    }
    if (bias) {
        rx += bias[2 * c2];
        ry += bias[2 * c2 + 1];
    }
    float2* o2 = reinterpret_cast<float2*>(d_S + outOff);
    o2[n * (outS >> 1) + c2] = make_float2(rx, ry);
    if (outH) outH[n * CP + c2] = __floats2half2_rn(rx, ry);
}

// ---------------- GroupNorm + ReLU; writes fp16 hi+res (for HMMA) or fp32 ----------------
template<int C, int GS>
__global__ void k_gnorm(const float* __restrict__ gamma, const float* __restrict__ beta,
                        int srcOff, __half* __restrict__ dstH, __half* __restrict__ dstR,
                        int dstOffF) {
    int idx = blockIdx.x * blockDim.x + threadIdx.x;
    if (idx >= NN * C) return;
    int c = idx & (C - 1);
    float v = d_S[srcOff + idx];
    float s = v, q = v * v;
#pragma unroll
    for (int o = GS / 2; o; o >>= 1) {
        s += __shfl_xor_sync(0xffffffffu, s, o);
        q += __shfl_xor_sync(0xffffffffu, q, o);
    }
    float mean = s * (1.0f / GS);
    float var = fmaxf(q * (1.0f / GS) - mean * mean, 0.0f);
    float y = (v - mean) * rsqrtf(var + 1e-5f);
    y = fmaxf(fmaf(y, gamma[c], beta[c]), 0.0f);
    if (dstH) {
        __half h = __float2half_rn(y);
        dstH[idx] = h;
        dstR[idx] = __float2half_rn(y - __half2float(h));
    } else {
        d_S[dstOffF + idx] = y;
    }
}

// ---------------- final projection: [16,320000] @ [320000,128], split-K ----------------
__global__ void __launch_bounds__(128) k_final(const float* __restrict__ Wl) {
    const int CHUNK = 320;                  // 1000 blocks * 320 = 320000
    int blk = blockIdx.x;
    int t = threadIdx.x;
    int j0base = blk * CHUNK;
    float acc[BB];
#pragma unroll
    for (int b = 0; b < BB; b++) acc[b] = 0.0f;
    __shared__ float Hs[BB][32];
    for (int jt = 0; jt < CHUNK; jt += 32) {
        int j0 = j0base + jt;
        for (int i = t; i < BB * 32; i += 128) {
            int b = i >> 5, jj = i & 31;
            Hs[b][jj] = d_S[OFF_H3 + b * 320000 + j0 + jj];
        }
        __syncthreads();
#pragma unroll
        for (int jj = 0; jj < 32; jj++) {
            float w = Wl[(j0 + jj) * 128 + t];
#pragma unroll
            for (int b = 0; b < BB; b++)
                acc[b] = fmaf(Hs[b][jj], w, acc[b]);
        }
        __syncthreads();
    }
#pragma unroll
    for (int b = 0; b < BB; b++)
        d_part[blk * 2048 + b * 128 + t] = acc[b];
}

__global__ void k_reduce(const float* __restrict__ bl, float* __restrict__ out) {
    int o = blockIdx.x;
    int t = threadIdx.x;
    float s = 0.0f;
    for (int p = t; p < 1000; p += 32) s += d_part[p * 2048 + o];
#pragma unroll
    for (int off = 16; off; off >>= 1)
        s += __shfl_down_sync(0xffffffffu, s, off);
    if (t == 0) out[o] = s + bl[o & 127];
}

// ---------------- launch ----------------
extern "C" void kernel_launch(void* const* d_in, const int* in_sizes, int n_in,
                              void* d_out, int out_size) {
    const float* x  = (const float*)d_in[0];
    const int*   ei = (const int*)d_in[1];          // int32 (JAX x64 disabled)
    const float* W0 = (const float*)d_in[2];
    const float* b0 = (const float*)d_in[3];
    const float* g0 = (const float*)d_in[4];
    const float* be0 = (const float*)d_in[5];
    const float* W1 = (const float*)d_in[6];
    const float* b1 = (const float*)d_in[7];
    const float* g1 = (const float*)d_in[8];
    const float* be1 = (const float*)d_in[9];
    const float* W2 = (const float*)d_in[10];
    const float* b2 = (const float*)d_in[11];
    const float* g2 = (const float*)d_in[12];
    const float* be2 = (const float*)d_in[13];
    const float* Wl = (const float*)d_in[14];
    const float* bl = (const float*)d_in[15];
    float* out = (float*)d_out;

    __half *Hh, *Hr, *Wth, *Wtr;
    __half2 *H0, *H1;
    cudaGetSymbolAddress((void**)&Hh, d_Hh);
    cudaGetSymbolAddress((void**)&Hr, d_Hr);
    cudaGetSymbolAddress((void**)&Wth, d_Wth);
    cudaGetSymbolAddress((void**)&Wtr, d_Wtr);
    cudaGetSymbolAddress((void**)&H0, d_Bh0);
    cudaGetSymbolAddress((void**)&H1, d_Bh1);

    // --- graph preprocessing + weight conversion ---
    k_zero_deg<<<cdiv(NN, 256), 256>>>();
    k_deg<<<cdiv(EE, 256), 256>>>(ei);
    k_dis<<<cdiv(NN, 256), 256>>>();
    int nblk = cdiv(NN, 1024);
    k_scan1<<<nblk, 1024>>>();
    k_scan2<<<1, 32>>>(nblk);
    k_scan3<<<cdiv(NN, 256), 256>>>();
    k_fill<<<cdiv(EE, 256), 256>>>(ei);
    k_wconv<<<cdiv(6 * 128 * 64, 256), 256>>>(W1, 128, 64, Wth, Wtr);
    k_wconv<<<cdiv(6 * 64 * 32, 256), 256>>>(W2, 64, 32, Wth + WT2_OFF, Wtr + WT2_OFF);

    // --- layer 0: standard recursion (cin=3 -> cout=128), Ktot=18 ---
    k_copy3<<<cdiv(NN, 256), 256>>>(x);
    k_prop3<<<cdiv(NN, 128), 128>>>(0, -1, 1, 1.0f);
    k_prop3<<<cdiv(NN, 128), 128>>>(1, 0, 2, 2.0f);
    k_prop3<<<cdiv(NN, 128), 128>>>(2, 1, 3, 2.0f);
    k_prop3<<<cdiv(NN, 128), 128>>>(3, 2, 4, 2.0f);
    k_prop3<<<cdiv(NN, 128), 128>>>(4, 3, 5, 2.0f);
    k_gemm<128, 8><<<NN / 128, 256>>>(18, OFF_A18, 18, OFF_OUT, 128, W0, b0);
    k_gnorm<128, 16><<<cdiv(NN * 128, 256), 256>>>(g0, be0, OFF_OUT, Hh, Hr, 0);

    // --- layer 1 (cin=128 -> cout=64): P_k = H@W1_k (split-fp16 HMMA), then Clenshaw ---
    k_hgemm<128, 64><<<dim3(NN / 128, 6), 256>>>(Hh, Hr, Wth, Wtr, OFF_P);
    {
        const int P5 = OFF_P + 5 * 64, P4 = OFF_P + 4 * 64, P3 = OFF_P + 3 * 64;
        const int P2 = OFF_P + 2 * 64, P1 = OFF_P + 1 * 64, P0 = OFF_P;
        dim3 blk(32, 4); int g = NN / 4;
        k_f2h<<<cdiv(NN * 32, 256), 256>>>(P5, 384, 32, H0);
        k_clenshaw<64><<<g, blk>>>(H0, -1, 0, P4, 384, OFF_B0, 64, H1, 2.0f, 0);
        k_clenshaw<64><<<g, blk>>>(H1, P5, 384, P3, 384, OFF_B1, 64, H0, 2.0f, 0);
        k_clenshaw<64><<<g, blk>>>(H0, OFF_B0, 64, P2, 384, OFF_B2, 64, H1, 2.0f, 0);
        k_clenshaw<64><<<g, blk>>>(H1, OFF_B1, 64, P1, 384, OFF_B0, 64, H0, 2.0f, 0);
        k_clenshaw<64><<<g, blk>>>(H0, OFF_B2, 64, P0, 384, OFF_OUT, 64, (__half2*)0, 1.0f, b1);
    }
    k_gnorm<64, 8><<<cdiv(NN * 64, 256), 256>>>(g1, be1, OFF_OUT, Hh, Hr, 0);

    // --- layer 2 (cin=64 -> cout=32): P_k = H@W2_k (split-fp16 HMMA), then Clenshaw ---
    k_hgemm<64, 32><<<dim3(NN / 128, 6), 256>>>(Hh, Hr, Wth + WT2_OFF, Wtr + WT2_OFF, OFF_P);
    {
        const int P5 = OFF_P + 5 * 32, P4 = OFF_P + 4 * 32, P3 = OFF_P + 3 * 32;
        const int P2 = OFF_P + 2 * 32, P1 = OFF_P + 1 * 32, P0 = OFF_P;
        dim3 blk(16, 8); int g = NN / 8;
        k_f2h<<<cdiv(NN * 16, 256), 256>>>(P5, 192, 16, H0);
        k_clenshaw<32><<<g, blk>>>(H0, -1, 0, P4, 192, OFF_B0, 32, H1, 2.0f, 0);
        k_clenshaw<32><<<g, blk>>>(H1, P5, 192, P3, 192, OFF_B1, 32, H0, 2.0f, 0);
        k_clenshaw<32><<<g, blk>>>(H0, OFF_B0, 32, P2, 192, OFF_B2, 32, H1, 2.0f, 0);
        k_clenshaw<32><<<g, blk>>>(H1, OFF_B1, 32, P1, 192, OFF_B0, 32, H0, 2.0f, 0);
        k_clenshaw<32><<<g, blk>>>(H0, OFF_B2, 32, P0, 192, OFF_OUT, 32, (__half2*)0, 1.0f, b2);
    }
    k_gnorm<32, 4><<<cdiv(NN * 32, 256), 256>>>(g2, be2, OFF_OUT, (__half*)0, (__half*)0, OFF_H3);

    // --- final projection ---
    k_final<<<1000, 128>>>(Wl);
    k_reduce<<<2048, 32>>>(bl, out);
}

// round 11
// speedup vs baseline: 2.1053x; 1.0671x over previous
#include <cuda_runtime.h>
#include <cuda_fp16.h>
#include <math.h>

#define NN 160000
#define EE 2560000
#define BB 16

// ---- scratch arena layout (floats) ----
#define OFF_A4   0                    // 6 slabs * NN float4 : layer0 Cheb slabs
#define OFF_A18  3840000              // NN*18 : packed layer0 slabs for GEMM
#define OFF_P    6720000              // NN*384 : P_k = H @ W_k slabs
#define OFF_B0   68160000             // NN*64 : Clenshaw b buffers (fp32)
#define OFF_B1   78400000
#define OFF_B2   88640000
#define OFF_OUT  98880000             // NN*128 : layer0 conv output pre-GroupNorm
#define OFF_H3   119360000            // NN*32 : final activations
__device__ float d_S[124480000];      // ~498 MB

__device__ __half d_Hh[NN * 128];     // fp16 hi of post-GN activations (GEMM A)
__device__ __half d_Hr[NN * 128];     // fp16 residual of A
#define WT_TOT (6 * 64 * 128 + 6 * 32 * 64)
__device__ __half d_Wth[WT_TOT];      // transposed fp16 hi weights
__device__ __half d_Wtr[WT_TOT];      // transposed fp16 residual weights
#define WT2_OFF (6 * 64 * 128)

__device__ __half2 d_Bh0[NN * 32];    // half shadow of b (gather path), ping
__device__ __half2 d_Bh1[NN * 32];    // pong

__device__ int   d_deg[NN];
__device__ float d_dis[NN];
__device__ int   d_rowptr[NN + 1];
__device__ int   d_cursor[NN];
__device__ int   d_colind[EE];
__device__ float d_val[EE];
__device__ int   d_blocksum[160];
__device__ float d_part[1000 * 2048];

static inline int cdiv(int a, int b) { return (a + b - 1) / b; }

// packed f32x2 helpers (L0 SGEMM)
__device__ __forceinline__ unsigned long long pack2(float x, float y) {
    unsigned long long r;
    asm("mov.b64 %0, {%1, %2};" : "=l"(r) : "r"(__float_as_uint(x)), "r"(__float_as_uint(y)));
    return r;
}
__device__ __forceinline__ void unpack2(unsigned long long p, float& x, float& y) {
    unsigned int lo, hi;
    asm("mov.b64 {%0, %1}, %2;" : "=r"(lo), "=r"(hi) : "l"(p));
    x = __uint_as_float(lo); y = __uint_as_float(hi);
}
__device__ __forceinline__ void ffma2(unsigned long long& d, unsigned long long a, unsigned long long b) {
    asm("fma.rn.f32x2 %0, %1, %2, %3;" : "=l"(d) : "l"(a), "l"(b), "l"(d));
}
__device__ __forceinline__ void mma_f16(float* acc, const unsigned* a, unsigned b0, unsigned b1) {
    asm volatile(
        "mma.sync.aligned.m16n8k16.row.col.f32.f16.f16.f32 "
        "{%0,%1,%2,%3}, {%4,%5,%6,%7}, {%8,%9}, {%0,%1,%2,%3};"
        : "+f"(acc[0]), "+f"(acc[1]), "+f"(acc[2]), "+f"(acc[3])
        : "r"(a[0]), "r"(a[1]), "r"(a[2]), "r"(a[3]), "r"(b0), "r"(b1));
}

// ---------------- graph preprocessing ----------------
__global__ void k_zero_deg() {
    int i = blockIdx.x * blockDim.x + threadIdx.x;
    if (i < NN) d_deg[i] = 0;
}
__global__ void k_deg(const int* __restrict__ ei) {
    int e = blockIdx.x * blockDim.x + threadIdx.x;
    if (e < EE) atomicAdd(&d_deg[ei[e]], 1);
}
__global__ void k_dis() {
    int i = blockIdx.x * blockDim.x + threadIdx.x;
    if (i < NN) {
        int dg = d_deg[i];
        d_dis[i] = (dg > 0) ? rsqrtf((float)dg) : 0.0f;
    }
}
__global__ void k_scan1() {
    __shared__ int s[1024];
    int t = threadIdx.x;
    int idx = blockIdx.x * 1024 + t;
    int v = (idx < NN) ? d_deg[idx] : 0;
    s[t] = v;
    __syncthreads();
    for (int o = 1; o < 1024; o <<= 1) {
        int x = (t >= o) ? s[t - o] : 0;
        __syncthreads();
        s[t] += x;
        __syncthreads();
    }
    if (idx < NN) d_rowptr[idx] = s[t] - v;
    if (t == 1023) d_blocksum[blockIdx.x] = s[t];
}
__global__ void k_scan2(int nblk) {
    if (threadIdx.x == 0 && blockIdx.x == 0) {
        int run = 0;
        for (int i = 0; i < nblk; i++) {
            int u = d_blocksum[i];
            d_blocksum[i] = run;
            run += u;
        }
        d_rowptr[NN] = run;
    }
}
__global__ void k_scan3() {
    int i = blockIdx.x * blockDim.x + threadIdx.x;
    if (i < NN) {
        int r = d_rowptr[i] + d_blocksum[i >> 10];
        d_rowptr[i] = r;
        d_cursor[i] = r;
    }
}
__global__ void k_fill(const int* __restrict__ ei) {
    int e = blockIdx.x * blockDim.x + threadIdx.x;
    if (e < EE) {
        int r = ei[e];
        int c = ei[EE + e];
        int p = atomicAdd(&d_cursor[r], 1);
        d_colind[p] = c;
        d_val[p] = -d_dis[r] * d_dis[c];
    }
}

// ---------------- weight convert+transpose (hi + residual) ----------------
__global__ void k_wconv(const float* __restrict__ W, int CIN, int COUT,
                        __half* __restrict__ oh, __half* __restrict__ orr) {
    int idx = blockIdx.x * blockDim.x + threadIdx.x;
    int tot = 6 * CIN * COUT;
    if (idx >= tot) return;
    int k = idx / (CIN * COUT);
    int rem = idx - k * (CIN * COUT);
    int c = rem / CIN;
    int j = rem - c * CIN;
    float v = W[(k * CIN + j) * COUT + c];
    __half h = __float2half_rn(v);
    oh[(k * COUT + c) * CIN + j] = h;
    orr[(k * COUT + c) * CIN + j] = __float2half_rn(v - __half2float(h));
}

// ---------------- layer 0: copy x + standard Chebyshev recursion (cin=3, float4 slabs) ----------------
__global__ void k_copy3(const float* __restrict__ x) {
    int n = blockIdx.x * blockDim.x + threadIdx.x;
    if (n >= NN) return;
    float a = x[3 * n], b = x[3 * n + 1], c = x[3 * n + 2];
    float4* A4 = reinterpret_cast<float4*>(d_S + OFF_A4);
    A4[n] = make_float4(a, b, c, 0.0f);
    float* pk = d_S + OFF_A18 + n * 18;
    pk[0] = a; pk[1] = b; pk[2] = c;
}

__global__ void k_prop3(int si, int sp, int so, float alpha) {
    int n = blockIdx.x * blockDim.x + threadIdx.x;
    if (n >= NN) return;
    int e0 = d_rowptr[n], e1 = d_rowptr[n + 1];
    float4* A4 = reinterpret_cast<float4*>(d_S + OFF_A4);
    const float4* __restrict__ in = A4 + (size_t)si * NN;
    float a0 = 0.f, a1 = 0.f, a2 = 0.f;
    int e = e0;
    for (; e + 4 <= e1; e += 4) {
        int i0 = d_colind[e],     i1 = d_colind[e + 1];
        int i2 = d_colind[e + 2], i3 = d_colind[e + 3];
        float v0 = d_val[e],     v1 = d_val[e + 1];
        float v2 = d_val[e + 2], v3 = d_val[e + 3];
        float4 q0 = __ldg(in + i0);
        float4 q1 = __ldg(in + i1);
        float4 q2 = __ldg(in + i2);
        float4 q3 = __ldg(in + i3);
        a0 = fmaf(v0, q0.x, a0); a1 = fmaf(v0, q0.y, a1); a2 = fmaf(v0, q0.z, a2);
        a0 = fmaf(v1, q1.x, a0); a1 = fmaf(v1, q1.y, a1); a2 = fmaf(v1, q1.z, a2);
        a0 = fmaf(v2, q2.x, a0); a1 = fmaf(v2, q2.y, a1); a2 = fmaf(v2, q2.z, a2);
        a0 = fmaf(v3, q3.x, a0); a1 = fmaf(v3, q3.y, a1); a2 = fmaf(v3, q3.z, a2);
    }
    for (; e < e1; ++e) {
        int ci = d_colind[e];
        float v = d_val[e];
        float4 q = __ldg(in + ci);
        a0 = fmaf(v, q.x, a0);
        a1 = fmaf(v, q.y, a1);
        a2 = fmaf(v, q.z, a2);
    }
    float rx = alpha * a0, ry = alpha * a1, rz = alpha * a2;
    if (sp >= 0) {
        float4 pv = A4[(size_t)sp * NN + n];
        rx -= pv.x; ry -= pv.y; rz -= pv.z;
    }
    A4[(size_t)so * NN + n] = make_float4(rx, ry, rz, 0.0f);
    float* pk = d_S + OFF_A18 + n * 18 + so * 3;
    pk[0] = rx; pk[1] = ry; pk[2] = rz;
}

// ---------------- L0 SGEMM (fp32 FFMA2): d_OUT[N,128] = A18[N,18] @ W0[18,128] + b0 ----------------
template<int BN, int TN>
__global__ void __launch_bounds__(256) k_gemm(int Ktot, int aOff, int aStride,
                                              int outOff, int outStride,
                                              const float* __restrict__ W,
                                              const float* __restrict__ bias) {
    constexpr int BM = 128, BK = 16, TM = 8;
    __shared__ float As[BK][BM + 2];
    __shared__ float Ws[BK][BN];
    int tid = threadIdx.x;
    int tx = tid & 15, ty = tid >> 4;
    int rowBase = blockIdx.x * BM;

    unsigned long long acc2[TM / 2][TN];
#pragma unroll
    for (int i = 0; i < TM / 2; i++)
#pragma unroll
        for (int j = 0; j < TN; j++) acc2[i][j] = 0ull;

    for (int kk = 0; kk < Ktot; kk += BK) {
#pragma unroll
        for (int it = 0; it < (BM * BK) / 256; it++) {
            int i = tid + it * 256;
            int r = i >> 4, k = i & 15;
            int kg = kk + k;
            As[k][r] = (kg < Ktot) ? d_S[aOff + (rowBase + r) * aStride + kg] : 0.0f;
        }
#pragma unroll
        for (int it = 0; it < (BK * BN) / 256; it++) {
            int i = tid + it * 256;
            int k = i / BN, col = i - k * BN;
            int kg = kk + k;
            Ws[k][col] = (kg < Ktot) ? W[kg * BN + col] : 0.0f;
        }
        __syncthreads();
#pragma unroll
        for (int kb = 0; kb < BK; kb++) {
            unsigned long long a2[TM / 2], b2[TN];
            const float2* arow = reinterpret_cast<const float2*>(&As[kb][0]);
#pragma unroll
            for (int i = 0; i < TM / 2; i++) {
                float2 av = arow[ty * (TM / 2) + i];
                a2[i] = pack2(av.x, av.y);
            }
#pragma unroll
            for (int j = 0; j < TN; j++) {
                float bv = Ws[kb][tx * TN + j];
                b2[j] = pack2(bv, bv);
            }
#pragma unroll
            for (int i = 0; i < TM / 2; i++)
#pragma unroll
                for (int j = 0; j < TN; j++)
                    ffma2(acc2[i][j], a2[i], b2[j]);
        }
        __syncthreads();
    }
#pragma unroll
    for (int i = 0; i < TM / 2; i++) {
        int r0 = rowBase + ty * TM + 2 * i;
#pragma unroll
        for (int j = 0; j < TN; j++) {
            int col = tx * TN + j;
            float v0, v1;
            unpack2(acc2[i][j], v0, v1);
            if (bias) { float bv = bias[col]; v0 += bv; v1 += bv; }
            d_S[outOff + r0 * outStride + col] = v0;
            d_S[outOff + (r0 + 1) * outStride + col] = v1;
        }
    }
}

// ---------------- split-fp16 HMMA GEMM + fused slab-5 half shadow ----------------
// D = Ah*Wh + Ah*Wr + Ar*Wh  (fp32 accurate; Ar*Wr dropped, O(eps^2))
template<int KTOT, int BN>
__global__ void __launch_bounds__(256) k_hgemm(const __half* __restrict__ Ah,
                                               const __half* __restrict__ Ar,
                                               const __half* __restrict__ Wh,
                                               const __half* __restrict__ Wr,
                                               int outOff, __half2* __restrict__ outH5) {
    constexpr int NT = BN / 16;
    constexpr int SROW = KTOT + 8;
    constexpr int CP = BN / 2;
    __shared__ __half sBh[BN * SROW];
    __shared__ __half sBr[BN * SROW];
    int tid = threadIdx.x;
    int warp = tid >> 5, lane = tid & 31;
    int g = lane >> 2, t = lane & 3;
    int wm = warp >> 1, wn = warp & 1;
    int rowBase = blockIdx.x * 128;
    int slab = blockIdx.y;

    const __half* whs = Wh + slab * BN * KTOT;
    const __half* wrs = Wr + slab * BN * KTOT;
    for (int i = tid; i < BN * KTOT; i += 256) {
        int r = i / KTOT, c = i - r * KTOT;
        sBh[r * SROW + c] = whs[i];
        sBr[r * SROW + c] = wrs[i];
    }
    __syncthreads();

    float acc[2][NT][4];
#pragma unroll
    for (int mt = 0; mt < 2; mt++)
#pragma unroll
        for (int nt = 0; nt < NT; nt++)
#pragma unroll
            for (int q = 0; q < 4; q++) acc[mt][nt][q] = 0.0f;

    size_t aRow = (size_t)(rowBase + wm * 32 + g) * KTOT;

#pragma unroll
    for (int k16 = 0; k16 < KTOT; k16 += 16) {
        unsigned aH[2][4], aR[2][4];
#pragma unroll
        for (int mt = 0; mt < 2; mt++) {
            size_t base = aRow + (size_t)mt * 16 * KTOT + k16 + 2 * t;
            aH[mt][0] = *reinterpret_cast<const unsigned*>(Ah + base);
            aH[mt][1] = *reinterpret_cast<const unsigned*>(Ah + base + 8 * KTOT);
            aH[mt][2] = *reinterpret_cast<const unsigned*>(Ah + base + 8);
            aH[mt][3] = *reinterpret_cast<const unsigned*>(Ah + base + 8 * KTOT + 8);
            aR[mt][0] = *reinterpret_cast<const unsigned*>(Ar + base);
            aR[mt][1] = *reinterpret_cast<const unsigned*>(Ar + base + 8 * KTOT);
            aR[mt][2] = *reinterpret_cast<const unsigned*>(Ar + base + 8);
            aR[mt][3] = *reinterpret_cast<const unsigned*>(Ar + base + 8 * KTOT + 8);
        }
#pragma unroll
        for (int nt = 0; nt < NT; nt++) {
            int ncol = wn * (BN / 2) + nt * 8 + g;
            const __half* bph = sBh + ncol * SROW + k16 + 2 * t;
            const __half* bpr = sBr + ncol * SROW + k16 + 2 * t;
            unsigned bh0 = *reinterpret_cast<const unsigned*>(bph);
            unsigned bh1 = *reinterpret_cast<const unsigned*>(bph + 8);
            unsigned br0 = *reinterpret_cast<const unsigned*>(bpr);
            unsigned br1 = *reinterpret_cast<const unsigned*>(bpr + 8);
#pragma unroll
            for (int mt = 0; mt < 2; mt++) {
                mma_f16(acc[mt][nt], aH[mt], bh0, bh1);
                mma_f16(acc[mt][nt], aH[mt], br0, br1);
                mma_f16(acc[mt][nt], aR[mt], bh0, bh1);
            }
        }
    }

    const int outStride = 6 * BN;
    bool shadow = (slab == 5) && (outH5 != 0);
#pragma unroll
    for (int mt = 0; mt < 2; mt++) {
        int r0 = rowBase + wm * 32 + mt * 16 + g;
#pragma unroll
        for (int nt = 0; nt < NT; nt++) {
            int colL = wn * (BN / 2) + nt * 8 + 2 * t;
            int col = slab * BN + colL;
            *reinterpret_cast<float2*>(d_S + outOff + (size_t)r0 * outStride + col) =
                make_float2(acc[mt][nt][0], acc[mt][nt][1]);
            *reinterpret_cast<float2*>(d_S + outOff + (size_t)(r0 + 8) * outStride + col) =
                make_float2(acc[mt][nt][2], acc[mt][nt][3]);
            if (shadow) {
                outH5[(size_t)r0 * CP + (colL >> 1)] =
                    __floats2half2_rn(acc[mt][nt][0], acc[mt][nt][1]);
                outH5[(size_t)(r0 + 8) * CP + (colL >> 1)] =
                    __floats2half2_rn(acc[mt][nt][2], acc[mt][nt][3]);
            }
        }
    }
}

// ---------------- Clenshaw gather core (half2), unroll x8 ----------------
template<int CP>
__device__ __forceinline__ void cl_gather(const __half2* __restrict__ inH,
                                          int e0, int e1, int c2,
                                          float& ax, float& ay) {
    int e = e0;
    for (; e + 8 <= e1; e += 8) {
#pragma unroll
        for (int u = 0; u < 8; u++) {
            float v = d_val[e + u];
            float2 gq = __half22float2(inH[d_colind[e + u] * CP + c2]);
            ax = fmaf(v, gq.x, ax); ay = fmaf(v, gq.y, ay);
        }
    }
    for (; e + 4 <= e1; e += 4) {
#pragma unroll
        for (int u = 0; u < 4; u++) {
            float v = d_val[e + u];
            float2 gq = __half22float2(inH[d_colind[e + u] * CP + c2]);
            ax = fmaf(v, gq.x, ax); ay = fmaf(v, gq.y, ay);
        }
    }
    for (; e < e1; ++e) {
        float v = d_val[e];
        float2 gq = __half22float2(inH[d_colind[e] * CP + c2]);
        ax = fmaf(v, gq.x, ax); ay = fmaf(v, gq.y, ay);
    }
}

// ---------------- Clenshaw propagation (intermediate steps) ----------------
template<int W>
__global__ void __launch_bounds__(128) k_clenshaw(
    const __half2* __restrict__ inH,
    int prevOff, int prevS,
    int xOff, int xS, int outOff, int outS,
    __half2* __restrict__ outH, float alpha)
{
    constexpr int CP = W / 2;
    constexpr int ROWS = 128 / CP;
    int n = blockIdx.x * ROWS + threadIdx.y;
    if (n >= NN) return;
    int c2 = threadIdx.x;
    float ax = 0.0f, ay = 0.0f;
    cl_gather<CP>(inH, d_rowptr[n], d_rowptr[n + 1], c2, ax, ay);

    const float2* x2 = reinterpret_cast<const float2*>(d_S + xOff);
    float2 xv = x2[n * (xS >> 1) + c2];
    float rx = fmaf(alpha, ax, xv.x);
    float ry = fmaf(alpha, ay, xv.y);
    if (prevOff >= 0) {
        const float2* p2 = reinterpret_cast<const float2*>(d_S + prevOff);
        float2 pv = p2[n * (prevS >> 1) + c2];
        rx -= pv.x; ry -= pv.y;
    }
    float2* o2 = reinterpret_cast<float2*>(d_S + outOff);
    o2[n * (outS >> 1) + c2] = make_float2(rx, ry);
    outH[n * CP + c2] = __floats2half2_rn(rx, ry);
}

// ---------------- Final Clenshaw step + bias + GroupNorm + ReLU, fused ----------------
// out = L b1 - b2 + P0 + bias, then GN(8 groups)+ReLU.
// F16OUT=1: write Hh/Hr fp16 (next layer GEMM A). F16OUT=0: write fp32 at f32Off.
template<int W, int F16OUT>
__global__ void __launch_bounds__(128) k_clenshaw_gn(
    const __half2* __restrict__ inH,
    int prevOff, int prevS, int xOff, int xS,
    const float* __restrict__ bias,
    const float* __restrict__ gamma, const float* __restrict__ beta,
    __half* __restrict__ Hh, __half* __restrict__ Hr, int f32Off)
{
    constexpr int CP = W / 2;
    constexpr int ROWS = 128 / CP;
    constexpr int GS = W / 8;            // channels per group
    constexpr int LGL = GS / 2;          // lanes per group
    int n = blockIdx.x * ROWS + threadIdx.y;
    if (n >= NN) return;
    int c2 = threadIdx.x;
    float ax = 0.0f, ay = 0.0f;
    cl_gather<CP>(inH, d_rowptr[n], d_rowptr[n + 1], c2, ax, ay);

    const float2* x2 = reinterpret_cast<const float2*>(d_S + xOff);
    float2 xv = x2[n * (xS >> 1) + c2];
    const float2* p2 = reinterpret_cast<const float2*>(d_S + prevOff);
    float2 pv = p2[n * (prevS >> 1) + c2];
    float rx = ax + xv.x - pv.x + bias[2 * c2];
    float ry = ay + xv.y - pv.y + bias[2 * c2 + 1];

    // GroupNorm over GS channels (LGL lanes x 2 channels), warp shuffles
    float s = rx + ry;
    float q = rx * rx + ry * ry;
#pragma unroll
    for (int o = 1; o < LGL; o <<= 1) {
        s += __shfl_xor_sync(0xffffffffu, s, o);
        q += __shfl_xor_sync(0xffffffffu, q, o);
    }
    float mean = s * (1.0f / GS);
    float var = fmaxf(q * (1.0f / GS) - mean * mean, 0.0f);
    float inv = rsqrtf(var + 1e-5f);
    float y0 = fmaxf(fmaf((rx - mean) * inv, gamma[2 * c2],     beta[2 * c2]),     0.0f);
    float y1 = fmaxf(fmaf((ry - mean) * inv, gamma[2 * c2 + 1], beta[2 * c2 + 1]), 0.0f);

    if (F16OUT) {
        __half h0 = __float2half_rn(y0), h1 = __float2half_rn(y1);
        *reinterpret_cast<__half2*>(Hh + (size_t)n * W + 2 * c2) =
            __halves2half2(h0, h1);
        *reinterpret_cast<__half2*>(Hr + (size_t)n * W + 2 * c2) =
            __floats2half2_rn(y0 - __half2float(h0), y1 - __half2float(h1));
    } else {
        float2* o2 = reinterpret_cast<float2*>(d_S + f32Off);
        o2[n * CP + c2] = make_float2(y0, y1);
    }
}

// ---------------- GroupNorm + ReLU (layer 0 only) ----------------
template<int C, int GS>
__global__ void k_gnorm(const float* __restrict__ gamma, const float* __restrict__ beta,
                        int srcOff, __half* __restrict__ dstH, __half* __restrict__ dstR) {
    int idx = blockIdx.x * blockDim.x + threadIdx.x;
    if (idx >= NN * C) return;
    int c = idx & (C - 1);
    float v = d_S[srcOff + idx];
    float s = v, q = v * v;
#pragma unroll
    for (int o = GS / 2; o; o >>= 1) {
        s += __shfl_xor_sync(0xffffffffu, s, o);
        q += __shfl_xor_sync(0xffffffffu, q, o);
    }
    float mean = s * (1.0f / GS);
    float var = fmaxf(q * (1.0f / GS) - mean * mean, 0.0f);
    float y = (v - mean) * rsqrtf(var + 1e-5f);
    y = fmaxf(fmaf(y, gamma[c], beta[c]), 0.0f);
    __half h = __float2half_rn(y);
    dstH[idx] = h;
    dstR[idx] = __float2half_rn(y - __half2float(h));
}

// ---------------- final projection: [16,320000] @ [320000,128], split-K ----------------
__global__ void __launch_bounds__(128) k_final(const float* __restrict__ Wl) {
    const int CHUNK = 320;
    int blk = blockIdx.x;
    int t = threadIdx.x;
    int j0base = blk * CHUNK;
    float acc[BB];
#pragma unroll
    for (int b = 0; b < BB; b++) acc[b] = 0.0f;
    __shared__ float Hs[BB][32];
    for (int jt = 0; jt < CHUNK; jt += 32) {
        int j0 = j0base + jt;
        for (int i = t; i < BB * 32; i += 128) {
            int b = i >> 5, jj = i & 31;
            Hs[b][jj] = d_S[OFF_H3 + b * 320000 + j0 + jj];
        }
        __syncthreads();
#pragma unroll
        for (int jj = 0; jj < 32; jj++) {
            float w = Wl[(j0 + jj) * 128 + t];
#pragma unroll
            for (int b = 0; b < BB; b++)
                acc[b] = fmaf(Hs[b][jj], w, acc[b]);
        }
        __syncthreads();
    }
#pragma unroll
    for (int b = 0; b < BB; b++)
        d_part[blk * 2048 + b * 128 + t] = acc[b];
}

__global__ void k_reduce(const float* __restrict__ bl, float* __restrict__ out) {
    int o = blockIdx.x;
    int t = threadIdx.x;
    float s = 0.0f;
    for (int p = t; p < 1000; p += 32) s += d_part[p * 2048 + o];
#pragma unroll
    for (int off = 16; off; off >>= 1)
        s += __shfl_down_sync(0xffffffffu, s, off);
    if (t == 0) out[o] = s + bl[o & 127];
}

// ---------------- launch ----------------
extern "C" void kernel_launch(void* const* d_in, const int* in_sizes, int n_in,
                              void* d_out, int out_size) {
    const float* x  = (const float*)d_in[0];
    const int*   ei = (const int*)d_in[1];          // int32 (JAX x64 disabled)
    const float* W0 = (const float*)d_in[2];
    const float* b0 = (const float*)d_in[3];
    const float* g0 = (const float*)d_in[4];
    const float* be0 = (const float*)d_in[5];
    const float* W1 = (const float*)d_in[6];
    const float* b1 = (const float*)d_in[7];
    const float* g1 = (const float*)d_in[8];
    const float* be1 = (const float*)d_in[9];
    const float* W2 = (const float*)d_in[10];
    const float* b2 = (const float*)d_in[11];
    const float* g2 = (const float*)d_in[12];
    const float* be2 = (const float*)d_in[13];
    const float* Wl = (const float*)d_in[14];
    const float* bl = (const float*)d_in[15];
    float* out = (float*)d_out;

    __half *Hh, *Hr, *Wth, *Wtr;
    __half2 *H0, *H1;
    cudaGetSymbolAddress((void**)&Hh, d_Hh);
    cudaGetSymbolAddress((void**)&Hr, d_Hr);
    cudaGetSymbolAddress((void**)&Wth, d_Wth);
    cudaGetSymbolAddress((void**)&Wtr, d_Wtr);
    cudaGetSymbolAddress((void**)&H0, d_Bh0);
    cudaGetSymbolAddress((void**)&H1, d_Bh1);

    // --- graph preprocessing + weight conversion ---
    k_zero_deg<<<cdiv(NN, 256), 256>>>();
    k_deg<<<cdiv(EE, 256), 256>>>(ei);
    k_dis<<<cdiv(NN, 256), 256>>>();
    int nblk = cdiv(NN, 1024);
    k_scan1<<<nblk, 1024>>>();
    k_scan2<<<1, 32>>>(nblk);
    k_scan3<<<cdiv(NN, 256), 256>>>();
    k_fill<<<cdiv(EE, 256), 256>>>(ei);
    k_wconv<<<cdiv(6 * 128 * 64, 256), 256>>>(W1, 128, 64, Wth, Wtr);
    k_wconv<<<cdiv(6 * 64 * 32, 256), 256>>>(W2, 64, 32, Wth + WT2_OFF, Wtr + WT2_OFF);

    // --- layer 0: standard recursion (cin=3 -> cout=128), Ktot=18 ---
    k_copy3<<<cdiv(NN, 256), 256>>>(x);
    k_prop3<<<cdiv(NN, 128), 128>>>(0, -1, 1, 1.0f);
    k_prop3<<<cdiv(NN, 128), 128>>>(1, 0, 2, 2.0f);
    k_prop3<<<cdiv(NN, 128), 128>>>(2, 1, 3, 2.0f);
    k_prop3<<<cdiv(NN, 128), 128>>>(3, 2, 4, 2.0f);
    k_prop3<<<cdiv(NN, 128), 128>>>(4, 3, 5, 2.0f);
    k_gemm<128, 8><<<NN / 128, 256>>>(18, OFF_A18, 18, OFF_OUT, 128, W0, b0);
    k_gnorm<128, 16><<<cdiv(NN * 128, 256), 256>>>(g0, be0, OFF_OUT, Hh, Hr);

    // --- layer 1 (cin=128 -> cout=64): split-fp16 HMMA (+slab5 shadow), Clenshaw, fused GN ---
    k_hgemm<128, 64><<<dim3(NN / 128, 6), 256>>>(Hh, Hr, Wth, Wtr, OFF_P, H0);
    {
        const int P5 = OFF_P + 5 * 64, P4 = OFF_P + 4 * 64, P3 = OFF_P + 3 * 64;
        const int P2 = OFF_P + 2 * 64, P1 = OFF_P + 1 * 64, P0 = OFF_P;
        dim3 blk(32, 4); int g = NN / 4;
        k_clenshaw<64><<<g, blk>>>(H0, -1, 0, P4, 384, OFF_B0, 64, H1, 2.0f);
        k_clenshaw<64><<<g, blk>>>(H1, P5, 384, P3, 384, OFF_B1, 64, H0, 2.0f);
        k_clenshaw<64><<<g, blk>>>(H0, OFF_B0, 64, P2, 384, OFF_B2, 64, H1, 2.0f);
        k_clenshaw<64><<<g, blk>>>(H1, OFF_B1, 64, P1, 384, OFF_B0, 64, H0, 2.0f);
        k_clenshaw_gn<64, 1><<<g, blk>>>(H0, OFF_B2, 64, P0, 384, b1, g1, be1, Hh, Hr, 0);
    }

    // --- layer 2 (cin=64 -> cout=32): split-fp16 HMMA (+slab5 shadow), Clenshaw, fused GN ---
    k_hgemm<64, 32><<<dim3(NN / 128, 6), 256>>>(Hh, Hr, Wth + WT2_OFF, Wtr + WT2_OFF, OFF_P, H0);
    {
        const int P5 = OFF_P + 5 * 32, P4 = OFF_P + 4 * 32, P3 = OFF_P + 3 * 32;
        const int P2 = OFF_P + 2 * 32, P1 = OFF_P + 1 * 32, P0 = OFF_P;
        dim3 blk(16, 8); int g = NN / 8;
        k_clenshaw<32><<<g, blk>>>(H0, -1, 0, P4, 192, OFF_B0, 32, H1, 2.0f);
        k_clenshaw<32><<<g, blk>>>(H1, P5, 192, P3, 192, OFF_B1, 32, H0, 2.0f);
        k_clenshaw<32><<<g, blk>>>(H0, OFF_B0, 32, P2, 192, OFF_B2, 32, H1, 2.0f);
        k_clenshaw<32><<<g, blk>>>(H1, OFF_B1, 32, P1, 192, OFF_B0, 32, H0, 2.0f);
        k_clenshaw_gn<32, 0><<<g, blk>>>(H0, OFF_B2, 32, P0, 192, b2, g2, be2,
                                         (__half*)0, (__half*)0, OFF_H3);
    }

    // --- final projection ---
    k_final<<<1000, 128>>>(Wl);
    k_reduce<<<2048, 32>>>(bl, out);
}

// round 12
// speedup vs baseline: 2.2363x; 1.0622x over previous
#include <cuda_runtime.h>
#include <cuda_fp16.h>
#include <math.h>

#define NN 160000
#define EE 2560000
#define BB 16

// ---- scratch arena layout (floats) ----
#define OFF_A4   0                    // 6 slabs * NN float4 : layer0 Cheb slabs
#define OFF_P    6720000              // NN*384 : P_k = H @ W_k slabs
#define OFF_B0   68160000             // NN*64 : Clenshaw b buffers (fp32)
#define OFF_B1   78400000
#define OFF_B2   88640000
#define OFF_H3   119360000            // NN*32 : final activations
__device__ float d_S[124480000];      // ~498 MB

__device__ __half d_Hh[NN * 128];     // fp16 hi of post-GN activations (GEMM A)
__device__ __half d_Hr[NN * 128];     // fp16 residual of A
#define WT_TOT (6 * 64 * 128 + 6 * 32 * 64)
__device__ __half d_Wth[WT_TOT];      // transposed fp16 hi weights
__device__ __half d_Wtr[WT_TOT];      // transposed fp16 residual weights
#define WT2_OFF (6 * 64 * 128)

__device__ __half2 d_Bh0[NN * 32];    // half shadow of b (gather path), ping
__device__ __half2 d_Bh1[NN * 32];    // pong

__device__ int   d_deg[NN];
__device__ int   d_rowptr[NN + 1];
__device__ int   d_cursor[NN];
__device__ int   d_colind[EE];
__device__ float d_val[EE];
__device__ int   d_blocksum[160];
__device__ float d_part[1000 * 2048];

static inline int cdiv(int a, int b) { return (a + b - 1) / b; }

__device__ __forceinline__ void mma_f16(float* acc, const unsigned* a, unsigned b0, unsigned b1) {
    asm volatile(
        "mma.sync.aligned.m16n8k16.row.col.f32.f16.f16.f32 "
        "{%0,%1,%2,%3}, {%4,%5,%6,%7}, {%8,%9}, {%0,%1,%2,%3};"
        : "+f"(acc[0]), "+f"(acc[1]), "+f"(acc[2]), "+f"(acc[3])
        : "r"(a[0]), "r"(a[1]), "r"(a[2]), "r"(a[3]), "r"(b0), "r"(b1));
}

// ---------------- graph preprocessing ----------------
__global__ void k_zero_deg() {
    int i = blockIdx.x * blockDim.x + threadIdx.x;
    if (i < NN) d_deg[i] = 0;
}
__global__ void k_deg(const int* __restrict__ ei) {
    int e = blockIdx.x * blockDim.x + threadIdx.x;
    if (e < EE) atomicAdd(&d_deg[ei[e]], 1);
}
__global__ void k_scan1() {
    __shared__ int s[1024];
    int t = threadIdx.x;
    int idx = blockIdx.x * 1024 + t;
    int v = (idx < NN) ? d_deg[idx] : 0;
    s[t] = v;
    __syncthreads();
    for (int o = 1; o < 1024; o <<= 1) {
        int x = (t >= o) ? s[t - o] : 0;
        __syncthreads();
        s[t] += x;
        __syncthreads();
    }
    if (idx < NN) d_rowptr[idx] = s[t] - v;
    if (t == 1023) d_blocksum[blockIdx.x] = s[t];
}
// single-warp chunked exclusive scan over nblk block sums
__global__ void k_scan2(int nblk) {
    int lane = threadIdx.x;
    int base = lane * 5;
    int v[5]; int s = 0;
#pragma unroll
    for (int u = 0; u < 5; u++) {
        int idx = base + u;
        v[u] = (idx < nblk) ? d_blocksum[idx] : 0;
        s += v[u];
    }
    int inc = s;
#pragma unroll
    for (int o = 1; o < 32; o <<= 1) {
        int t = __shfl_up_sync(0xffffffffu, inc, o);
        if (lane >= o) inc += t;
    }
    int run = inc - s;   // exclusive prefix of this lane's chunk
#pragma unroll
    for (int u = 0; u < 5; u++) {
        int idx = base + u;
        if (idx < nblk) d_blocksum[idx] = run;
        run += v[u];
    }
    if (lane == 31) d_rowptr[NN] = inc;
}
__global__ void k_scan3() {
    int i = blockIdx.x * blockDim.x + threadIdx.x;
    if (i < NN) {
        int r = d_rowptr[i] + d_blocksum[i >> 10];
        d_rowptr[i] = r;
        d_cursor[i] = r;
    }
}
// fill CSR; edge weight computed inline from degrees (deg[r]>=1 guaranteed)
__global__ void k_fill(const int* __restrict__ ei) {
    int e = blockIdx.x * blockDim.x + threadIdx.x;
    if (e < EE) {
        int r = ei[e];
        int c = ei[EE + e];
        int p = atomicAdd(&d_cursor[r], 1);
        d_colind[p] = c;
        int dc = d_deg[c];
        float wr = rsqrtf((float)d_deg[r]);
        float wc = (dc > 0) ? rsqrtf((float)dc) : 0.0f;
        d_val[p] = -wr * wc;
    }
}

// ---------------- weight convert+transpose (hi + residual) ----------------
__global__ void k_wconv(const float* __restrict__ W, int CIN, int COUT,
                        __half* __restrict__ oh, __half* __restrict__ orr) {
    int idx = blockIdx.x * blockDim.x + threadIdx.x;
    int tot = 6 * CIN * COUT;
    if (idx >= tot) return;
    int k = idx / (CIN * COUT);
    int rem = idx - k * (CIN * COUT);
    int c = rem / CIN;
    int j = rem - c * CIN;
    float v = W[(k * CIN + j) * COUT + c];
    __half h = __float2half_rn(v);
    oh[(k * COUT + c) * CIN + j] = h;
    orr[(k * COUT + c) * CIN + j] = __float2half_rn(v - __half2float(h));
}

// ---------------- layer 0: copy x + standard Chebyshev recursion (cin=3, float4 slabs) ----------------
__global__ void k_copy3(const float* __restrict__ x) {
    int n = blockIdx.x * blockDim.x + threadIdx.x;
    if (n >= NN) return;
    float4* A4 = reinterpret_cast<float4*>(d_S + OFF_A4);
    A4[n] = make_float4(x[3 * n], x[3 * n + 1], x[3 * n + 2], 0.0f);
}

__global__ void k_prop3(int si, int sp, int so, float alpha) {
    int n = blockIdx.x * blockDim.x + threadIdx.x;
    if (n >= NN) return;
    int e0 = d_rowptr[n], e1 = d_rowptr[n + 1];
    float4* A4 = reinterpret_cast<float4*>(d_S + OFF_A4);
    const float4* __restrict__ in = A4 + (size_t)si * NN;
    float a0 = 0.f, a1 = 0.f, a2 = 0.f;
    int e = e0;
    for (; e + 4 <= e1; e += 4) {
        int i0 = d_colind[e],     i1 = d_colind[e + 1];
        int i2 = d_colind[e + 2], i3 = d_colind[e + 3];
        float v0 = d_val[e],     v1 = d_val[e + 1];
        float v2 = d_val[e + 2], v3 = d_val[e + 3];
        float4 q0 = __ldg(in + i0);
        float4 q1 = __ldg(in + i1);
        float4 q2 = __ldg(in + i2);
        float4 q3 = __ldg(in + i3);
        a0 = fmaf(v0, q0.x, a0); a1 = fmaf(v0, q0.y, a1); a2 = fmaf(v0, q0.z, a2);
        a0 = fmaf(v1, q1.x, a0); a1 = fmaf(v1, q1.y, a1); a2 = fmaf(v1, q1.z, a2);
        a0 = fmaf(v2, q2.x, a0); a1 = fmaf(v2, q2.y, a1); a2 = fmaf(v2, q2.z, a2);
        a0 = fmaf(v3, q3.x, a0); a1 = fmaf(v3, q3.y, a1); a2 = fmaf(v3, q3.z, a2);
    }
    for (; e < e1; ++e) {
        int ci = d_colind[e];
        float v = d_val[e];
        float4 q = __ldg(in + ci);
        a0 = fmaf(v, q.x, a0);
        a1 = fmaf(v, q.y, a1);
        a2 = fmaf(v, q.z, a2);
    }
    float rx = alpha * a0, ry = alpha * a1, rz = alpha * a2;
    if (sp >= 0) {
        float4 pv = A4[(size_t)sp * NN + n];
        rx -= pv.x; ry -= pv.y; rz -= pv.z;
    }
    A4[(size_t)so * NN + n] = make_float4(rx, ry, rz, 0.0f);
}

// ---------------- fused L0 GEMM + GroupNorm + ReLU + fp16-split ----------------
// One warp per row: out[c] = b0[c] + sum_{k<18} a[k]*W0[k*128+c], GN(16ch groups), ReLU,
// write Hh/Hr. Lane handles cols {lane, lane+32, lane+64, lane+96}.
__global__ void __launch_bounds__(256) k_gemm0gn(
    const float* __restrict__ W0, const float* __restrict__ b0,
    const float* __restrict__ g0, const float* __restrict__ be0,
    __half* __restrict__ Hh, __half* __restrict__ Hr)
{
    __shared__ float sW[18 * 128];
    __shared__ float sB[128], sG[128], sBe[128];
    int tid = threadIdx.x;
    for (int i = tid; i < 18 * 128; i += 256) sW[i] = W0[i];
    if (tid < 128) { sB[tid] = b0[tid]; sG[tid] = g0[tid]; sBe[tid] = be0[tid]; }
    __syncthreads();
    int warp = tid >> 5, lane = tid & 31;
    int n = blockIdx.x * 8 + warp;
    const float4* A4 = reinterpret_cast<const float4*>(d_S + OFF_A4);
    float a[18];
#pragma unroll
    for (int k = 0; k < 6; k++) {
        float4 q = A4[(size_t)k * NN + n];
        a[3 * k] = q.x; a[3 * k + 1] = q.y; a[3 * k + 2] = q.z;
    }
    float y[4];
#pragma unroll
    for (int j = 0; j < 4; j++) {
        int c = lane + 32 * j;
        float acc = sB[c];
#pragma unroll
        for (int k = 0; k < 18; k++) acc = fmaf(a[k], sW[k * 128 + c], acc);
        y[j] = acc;
    }
    // GN: group = 16 consecutive channels = (half-warp, j) pair
#pragma unroll
    for (int j = 0; j < 4; j++) {
        float s = y[j], q = y[j] * y[j];
#pragma unroll
        for (int o = 1; o < 16; o <<= 1) {
            s += __shfl_xor_sync(0xffffffffu, s, o);
            q += __shfl_xor_sync(0xffffffffu, q, o);
        }
        float mean = s * (1.0f / 16.0f);
        float var = fmaxf(q * (1.0f / 16.0f) - mean * mean, 0.0f);
        float inv = rsqrtf(var + 1e-5f);
        int c = lane + 32 * j;
        float yy = fmaxf(fmaf((y[j] - mean) * inv, sG[c], sBe[c]), 0.0f);
        __half h = __float2half_rn(yy);
        Hh[(size_t)n * 128 + c] = h;
        Hr[(size_t)n * 128 + c] = __float2half_rn(yy - __half2float(h));
    }
}

// ---------------- split-fp16 HMMA GEMM + fused slab-5 half shadow ----------------
// D = Ah*Wh + Ah*Wr + Ar*Wh  (fp32 accurate; Ar*Wr dropped, O(eps^2))
template<int KTOT, int BN>
__global__ void __launch_bounds__(256) k_hgemm(const __half* __restrict__ Ah,
                                               const __half* __restrict__ Ar,
                                               const __half* __restrict__ Wh,
                                               const __half* __restrict__ Wr,
                                               int outOff, __half2* __restrict__ outH5) {
    constexpr int NT = BN / 16;
    constexpr int SROW = KTOT + 8;
    constexpr int CP = BN / 2;
    __shared__ __half sBh[BN * SROW];
    __shared__ __half sBr[BN * SROW];
    int tid = threadIdx.x;
    int warp = tid >> 5, lane = tid & 31;
    int g = lane >> 2, t = lane & 3;
    int wm = warp >> 1, wn = warp & 1;
    int rowBase = blockIdx.x * 128;
    int slab = blockIdx.y;

    const __half* whs = Wh + slab * BN * KTOT;
    const __half* wrs = Wr + slab * BN * KTOT;
    for (int i = tid; i < BN * KTOT; i += 256) {
        int r = i / KTOT, c = i - r * KTOT;
        sBh[r * SROW + c] = whs[i];
        sBr[r * SROW + c] = wrs[i];
    }
    __syncthreads();

    float acc[2][NT][4];
#pragma unroll
    for (int mt = 0; mt < 2; mt++)
#pragma unroll
        for (int nt = 0; nt < NT; nt++)
#pragma unroll
            for (int q = 0; q < 4; q++) acc[mt][nt][q] = 0.0f;

    size_t aRow = (size_t)(rowBase + wm * 32 + g) * KTOT;

#pragma unroll
    for (int k16 = 0; k16 < KTOT; k16 += 16) {
        unsigned aH[2][4], aR[2][4];
#pragma unroll
        for (int mt = 0; mt < 2; mt++) {
            size_t base = aRow + (size_t)mt * 16 * KTOT + k16 + 2 * t;
            aH[mt][0] = *reinterpret_cast<const unsigned*>(Ah + base);
            aH[mt][1] = *reinterpret_cast<const unsigned*>(Ah + base + 8 * KTOT);
            aH[mt][2] = *reinterpret_cast<const unsigned*>(Ah + base + 8);
            aH[mt][3] = *reinterpret_cast<const unsigned*>(Ah + base + 8 * KTOT + 8);
            aR[mt][0] = *reinterpret_cast<const unsigned*>(Ar + base);
            aR[mt][1] = *reinterpret_cast<const unsigned*>(Ar + base + 8 * KTOT);
            aR[mt][2] = *reinterpret_cast<const unsigned*>(Ar + base + 8);
            aR[mt][3] = *reinterpret_cast<const unsigned*>(Ar + base + 8 * KTOT + 8);
        }
#pragma unroll
        for (int nt = 0; nt < NT; nt++) {
            int ncol = wn * (BN / 2) + nt * 8 + g;
            const __half* bph = sBh + ncol * SROW + k16 + 2 * t;
            const __half* bpr = sBr + ncol * SROW + k16 + 2 * t;
            unsigned bh0 = *reinterpret_cast<const unsigned*>(bph);
            unsigned bh1 = *reinterpret_cast<const unsigned*>(bph + 8);
            unsigned br0 = *reinterpret_cast<const unsigned*>(bpr);
            unsigned br1 = *reinterpret_cast<const unsigned*>(bpr + 8);
#pragma unroll
            for (int mt = 0; mt < 2; mt++) {
                mma_f16(acc[mt][nt], aH[mt], bh0, bh1);
                mma_f16(acc[mt][nt], aH[mt], br0, br1);
                mma_f16(acc[mt][nt], aR[mt], bh0, bh1);
            }
        }
    }

    const int outStride = 6 * BN;
    bool shadow = (slab == 5) && (outH5 != 0);
#pragma unroll
    for (int mt = 0; mt < 2; mt++) {
        int r0 = rowBase + wm * 32 + mt * 16 + g;
#pragma unroll
        for (int nt = 0; nt < NT; nt++) {
            int colL = wn * (BN / 2) + nt * 8 + 2 * t;
            int col = slab * BN + colL;
            *reinterpret_cast<float2*>(d_S + outOff + (size_t)r0 * outStride + col) =
                make_float2(acc[mt][nt][0], acc[mt][nt][1]);
            *reinterpret_cast<float2*>(d_S + outOff + (size_t)(r0 + 8) * outStride + col) =
                make_float2(acc[mt][nt][2], acc[mt][nt][3]);
            if (shadow) {
                outH5[(size_t)r0 * CP + (colL >> 1)] =
                    __floats2half2_rn(acc[mt][nt][0], acc[mt][nt][1]);
                outH5[(size_t)(r0 + 8) * CP + (colL >> 1)] =
                    __floats2half2_rn(acc[mt][nt][2], acc[mt][nt][3]);
            }
        }
    }
}

// ---------------- Clenshaw gather core (half2), unroll x8 ----------------
template<int CP>
__device__ __forceinline__ void cl_gather(const __half2* __restrict__ inH,
                                          int e0, int e1, int c2,
                                          float& ax, float& ay) {
    int e = e0;
    for (; e + 8 <= e1; e += 8) {
#pragma unroll
        for (int u = 0; u < 8; u++) {
            float v = d_val[e + u];
            float2 gq = __half22float2(inH[d_colind[e + u] * CP + c2]);
            ax = fmaf(v, gq.x, ax); ay = fmaf(v, gq.y, ay);
        }
    }
    for (; e + 4 <= e1; e += 4) {
#pragma unroll
        for (int u = 0; u < 4; u++) {
            float v = d_val[e + u];
            float2 gq = __half22float2(inH[d_colind[e + u] * CP + c2]);
            ax = fmaf(v, gq.x, ax); ay = fmaf(v, gq.y, ay);
        }
    }
    for (; e < e1; ++e) {
        float v = d_val[e];
        float2 gq = __half22float2(inH[d_colind[e] * CP + c2]);
        ax = fmaf(v, gq.x, ax); ay = fmaf(v, gq.y, ay);
    }
}

// ---------------- Clenshaw propagation (intermediate steps) ----------------
template<int W>
__global__ void __launch_bounds__(128) k_clenshaw(
    const __half2* __restrict__ inH,
    int prevOff, int prevS,
    int xOff, int xS, int outOff, int outS,
    __half2* __restrict__ outH, float alpha)
{
    constexpr int CP = W / 2;
    constexpr int ROWS = 128 / CP;
    int n = blockIdx.x * ROWS + threadIdx.y;
    if (n >= NN) return;
    int c2 = threadIdx.x;
    float ax = 0.0f, ay = 0.0f;
    cl_gather<CP>(inH, d_rowptr[n], d_rowptr[n + 1], c2, ax, ay);

    const float2* x2 = reinterpret_cast<const float2*>(d_S + xOff);
    float2 xv = x2[n * (xS >> 1) + c2];
    float rx = fmaf(alpha, ax, xv.x);
    float ry = fmaf(alpha, ay, xv.y);
    if (prevOff >= 0) {
        const float2* p2 = reinterpret_cast<const float2*>(d_S + prevOff);
        float2 pv = p2[n * (prevS >> 1) + c2];
        rx -= pv.x; ry -= pv.y;
    }
    float2* o2 = reinterpret_cast<float2*>(d_S + outOff);
    o2[n * (outS >> 1) + c2] = make_float2(rx, ry);
    outH[n * CP + c2] = __floats2half2_rn(rx, ry);
}

// ---------------- Final Clenshaw step + bias + GroupNorm + ReLU, fused ----------------
template<int W, int F16OUT>
__global__ void __launch_bounds__(128) k_clenshaw_gn(
    const __half2* __restrict__ inH,
    int prevOff, int prevS, int xOff, int xS,
    const float* __restrict__ bias,
    const float* __restrict__ gamma, const float* __restrict__ beta,
    __half* __restrict__ Hh, __half* __restrict__ Hr, int f32Off)
{
    constexpr int CP = W / 2;
    constexpr int ROWS = 128 / CP;
    constexpr int GS = W / 8;
    constexpr int LGL = GS / 2;
    int n = blockIdx.x * ROWS + threadIdx.y;
    if (n >= NN) return;
    int c2 = threadIdx.x;
    float ax = 0.0f, ay = 0.0f;
    cl_gather<CP>(inH, d_rowptr[n], d_rowptr[n + 1], c2, ax, ay);

    const float2* x2 = reinterpret_cast<const float2*>(d_S + xOff);
    float2 xv = x2[n * (xS >> 1) + c2];
    const float2* p2 = reinterpret_cast<const float2*>(d_S + prevOff);
    float2 pv = p2[n * (prevS >> 1) + c2];
    float rx = ax + xv.x - pv.x + bias[2 * c2];
    float ry = ay + xv.y - pv.y + bias[2 * c2 + 1];

    float s = rx + ry;
    float q = rx * rx + ry * ry;
#pragma unroll
    for (int o = 1; o < LGL; o <<= 1) {
        s += __shfl_xor_sync(0xffffffffu, s, o);
        q += __shfl_xor_sync(0xffffffffu, q, o);
    }
    float mean = s * (1.0f / GS);
    float var = fmaxf(q * (1.0f / GS) - mean * mean, 0.0f);
    float inv = rsqrtf(var + 1e-5f);
    float y0 = fmaxf(fmaf((rx - mean) * inv, gamma[2 * c2],     beta[2 * c2]),     0.0f);
    float y1 = fmaxf(fmaf((ry - mean) * inv, gamma[2 * c2 + 1], beta[2 * c2 + 1]), 0.0f);

    if (F16OUT) {
        __half h0 = __float2half_rn(y0), h1 = __float2half_rn(y1);
        *reinterpret_cast<__half2*>(Hh + (size_t)n * W + 2 * c2) =
            __halves2half2(h0, h1);
        *reinterpret_cast<__half2*>(Hr + (size_t)n * W + 2 * c2) =
            __floats2half2_rn(y0 - __half2float(h0), y1 - __half2float(h1));
    } else {
        float2* o2 = reinterpret_cast<float2*>(d_S + f32Off);
        o2[n * CP + c2] = make_float2(y0, y1);
    }
}

// ---------------- final projection: [16,320000] @ [320000,128], split-K ----------------
__global__ void __launch_bounds__(128) k_final(const float* __restrict__ Wl) {
    const int CHUNK = 320;
    int blk = blockIdx.x;
    int t = threadIdx.x;
    int j0base = blk * CHUNK;
    float acc[BB];
#pragma unroll
    for (int b = 0; b < BB; b++) acc[b] = 0.0f;
    __shared__ float Hs[BB][32];
    for (int jt = 0; jt < CHUNK; jt += 32) {
        int j0 = j0base + jt;
        for (int i = t; i < BB * 32; i += 128) {
            int b = i >> 5, jj = i & 31;
            Hs[b][jj] = d_S[OFF_H3 + b * 320000 + j0 + jj];
        }
        __syncthreads();
#pragma unroll
        for (int jj = 0; jj < 32; jj++) {
            float w = Wl[(j0 + jj) * 128 + t];
#pragma unroll
            for (int b = 0; b < BB; b++)
                acc[b] = fmaf(Hs[b][jj], w, acc[b]);
        }
        __syncthreads();
    }
#pragma unroll
    for (int b = 0; b < BB; b++)
        d_part[blk * 2048 + b * 128 + t] = acc[b];
}

__global__ void k_reduce(const float* __restrict__ bl, float* __restrict__ out) {
    int o = blockIdx.x;
    int t = threadIdx.x;
    float s = 0.0f;
    for (int p = t; p < 1000; p += 32) s += d_part[p * 2048 + o];
#pragma unroll
    for (int off = 16; off; off >>= 1)
        s += __shfl_down_sync(0xffffffffu, s, off);
    if (t == 0) out[o] = s + bl[o & 127];
}

// ---------------- launch ----------------
extern "C" void kernel_launch(void* const* d_in, const int* in_sizes, int n_in,
                              void* d_out, int out_size) {
    const float* x  = (const float*)d_in[0];
    const int*   ei = (const int*)d_in[1];          // int32 (JAX x64 disabled)
    const float* W0 = (const float*)d_in[2];
    const float* b0 = (const float*)d_in[3];
    const float* g0 = (const float*)d_in[4];
    const float* be0 = (const float*)d_in[5];
    const float* W1 = (const float*)d_in[6];
    const float* b1 = (const float*)d_in[7];
    const float* g1 = (const float*)d_in[8];
    const float* be1 = (const float*)d_in[9];
    const float* W2 = (const float*)d_in[10];
    const float* b2 = (const float*)d_in[11];
    const float* g2 = (const float*)d_in[12];
    const float* be2 = (const float*)d_in[13];
    const float* Wl = (const float*)d_in[14];
    const float* bl = (const float*)d_in[15];
    float* out = (float*)d_out;

    __half *Hh, *Hr, *Wth, *Wtr;
    __half2 *H0, *H1;
    cudaGetSymbolAddress((void**)&Hh, d_Hh);
    cudaGetSymbolAddress((void**)&Hr, d_Hr);
    cudaGetSymbolAddress((void**)&Wth, d_Wth);
    cudaGetSymbolAddress((void**)&Wtr, d_Wtr);
    cudaGetSymbolAddress((void**)&H0, d_Bh0);
    cudaGetSymbolAddress((void**)&H1, d_Bh1);

    // --- graph preprocessing + weight conversion ---
    k_zero_deg<<<cdiv(NN, 256), 256>>>();
    k_deg<<<cdiv(EE, 256), 256>>>(ei);
    int nblk = cdiv(NN, 1024);
    k_scan1<<<nblk, 1024>>>();
    k_scan2<<<1, 32>>>(nblk);
    k_scan3<<<cdiv(NN, 256), 256>>>();
    k_fill<<<cdiv(EE, 256), 256>>>(ei);
    k_wconv<<<cdiv(6 * 128 * 64, 256), 256>>>(W1, 128, 64, Wth, Wtr);
    k_wconv<<<cdiv(6 * 64 * 32, 256), 256>>>(W2, 64, 32, Wth + WT2_OFF, Wtr + WT2_OFF);

    // --- layer 0: standard recursion (cin=3 -> cout=128), fused GEMM+GN ---
    k_copy3<<<cdiv(NN, 256), 256>>>(x);
    k_prop3<<<cdiv(NN, 128), 128>>>(0, -1, 1, 1.0f);
    k_prop3<<<cdiv(NN, 128), 128>>>(1, 0, 2, 2.0f);
    k_prop3<<<cdiv(NN, 128), 128>>>(2, 1, 3, 2.0f);
    k_prop3<<<cdiv(NN, 128), 128>>>(3, 2, 4, 2.0f);
    k_prop3<<<cdiv(NN, 128), 128>>>(4, 3, 5, 2.0f);
    k_gemm0gn<<<NN / 8, 256>>>(W0, b0, g0, be0, Hh, Hr);

    // --- layer 1 (cin=128 -> cout=64): split-fp16 HMMA (+slab5 shadow), Clenshaw, fused GN ---
    k_hgemm<128, 64><<<dim3(NN / 128, 6), 256>>>(Hh, Hr, Wth, Wtr, OFF_P, H0);
    {
        const int P5 = OFF_P + 5 * 64, P4 = OFF_P + 4 * 64, P3 = OFF_P + 3 * 64;
        const int P2 = OFF_P + 2 * 64, P1 = OFF_P + 1 * 64, P0 = OFF_P;
        dim3 blk(32, 4); int g = NN / 4;
        k_clenshaw<64><<<g, blk>>>(H0, -1, 0, P4, 384, OFF_B0, 64, H1, 2.0f);
        k_clenshaw<64><<<g, blk>>>(H1, P5, 384, P3, 384, OFF_B1, 64, H0, 2.0f);
        k_clenshaw<64><<<g, blk>>>(H0, OFF_B0, 64, P2, 384, OFF_B2, 64, H1, 2.0f);
        k_clenshaw<64><<<g, blk>>>(H1, OFF_B1, 64, P1, 384, OFF_B0, 64, H0, 2.0f);
        k_clenshaw_gn<64, 1><<<g, blk>>>(H0, OFF_B2, 64, P0, 384, b1, g1, be1, Hh, Hr, 0);
    }

    // --- layer 2 (cin=64 -> cout=32): split-fp16 HMMA (+slab5 shadow), Clenshaw, fused GN ---
    k_hgemm<64, 32><<<dim3(NN / 128, 6), 256>>>(Hh, Hr, Wth + WT2_OFF, Wtr + WT2_OFF, OFF_P, H0);
    {
        const int P5 = OFF_P + 5 * 32, P4 = OFF_P + 4 * 32, P3 = OFF_P + 3 * 32;
        const int P2 = OFF_P + 2 * 32, P1 = OFF_P + 1 * 32, P0 = OFF_P;
        dim3 blk(16, 8); int g = NN / 8;
        k_clenshaw<32><<<g, blk>>>(H0, -1, 0, P4, 192, OFF_B0, 32, H1, 2.0f);
        k_clenshaw<32><<<g, blk>>>(H1, P5, 192, P3, 192, OFF_B1, 32, H0, 2.0f);
        k_clenshaw<32><<<g, blk>>>(H0, OFF_B0, 32, P2, 192, OFF_B2, 32, H1, 2.0f);
        k_clenshaw<32><<<g, blk>>>(H1, OFF_B1, 32, P1, 192, OFF_B0, 32, H0, 2.0f);
        k_clenshaw_gn<32, 0><<<g, blk>>>(H0, OFF_B2, 32, P0, 192, b2, g2, be2,
                                         (__half*)0, (__half*)0, OFF_H3);
    }

    // --- final projection ---
    k_final<<<1000, 128>>>(Wl);
    k_reduce<<<2048, 32>>>(bl, out);
}

// round 13
// speedup vs baseline: 2.2492x; 1.0057x over previous
#include <cuda_runtime.h>
#include <cuda_fp16.h>
#include <math.h>

#define NN 160000
#define EE 2560000
#define BB 16

// ---- scratch arena layout (floats) ----
#define OFF_A4   0                    // 6 slabs * NN float4 : layer0 Cheb slabs
#define OFF_P    6720000              // NN*384 : P_k = H @ W_k slabs (fp32)
#define OFF_H3   119360000            // NN*32 : final activations
__device__ float d_S[124480000];      // ~498 MB

__device__ __half d_Hh[NN * 128];     // fp16 hi of post-GN activations (GEMM A)
__device__ __half d_Hr[NN * 128];     // fp16 residual of A
#define WT_TOT (6 * 64 * 128 + 6 * 32 * 64)
__device__ __half d_Wth[WT_TOT];      // transposed fp16 hi weights
__device__ __half d_Wtr[WT_TOT];      // transposed fp16 residual weights
#define WT2_OFF (6 * 64 * 128)

__device__ __half2 d_Bh0[NN * 32];    // fp16 Clenshaw b, ping
__device__ __half2 d_Bh1[NN * 32];    // pong

__device__ int   d_deg[NN];
__device__ int   d_rowptr[NN + 1];
__device__ int   d_cursor[NN];
__device__ int2  d_edge[EE];          // .x = colind, .y = bits(val)
__device__ int   d_blocksum[160];
__device__ float d_part[1000 * 2048];

static inline int cdiv(int a, int b) { return (a + b - 1) / b; }

__device__ __forceinline__ void mma_f16(float* acc, const unsigned* a, unsigned b0, unsigned b1) {
    asm volatile(
        "mma.sync.aligned.m16n8k16.row.col.f32.f16.f16.f32 "
        "{%0,%1,%2,%3}, {%4,%5,%6,%7}, {%8,%9}, {%0,%1,%2,%3};"
        : "+f"(acc[0]), "+f"(acc[1]), "+f"(acc[2]), "+f"(acc[3])
        : "r"(a[0]), "r"(a[1]), "r"(a[2]), "r"(a[3]), "r"(b0), "r"(b1));
}

// ---------------- graph preprocessing ----------------
__global__ void k_zero_deg() {
    int i = blockIdx.x * blockDim.x + threadIdx.x;
    if (i < NN) d_deg[i] = 0;
}
__global__ void k_deg(const int* __restrict__ ei) {
    int e = blockIdx.x * blockDim.x + threadIdx.x;
    if (e < EE) atomicAdd(&d_deg[ei[e]], 1);
}
__global__ void k_scan1() {
    __shared__ int s[1024];
    int t = threadIdx.x;
    int idx = blockIdx.x * 1024 + t;
    int v = (idx < NN) ? d_deg[idx] : 0;
    s[t] = v;
    __syncthreads();
    for (int o = 1; o < 1024; o <<= 1) {
        int x = (t >= o) ? s[t - o] : 0;
        __syncthreads();
        s[t] += x;
        __syncthreads();
    }
    if (idx < NN) d_rowptr[idx] = s[t] - v;
    if (t == 1023) d_blocksum[blockIdx.x] = s[t];
}
__global__ void k_scan2(int nblk) {
    int lane = threadIdx.x;
    int base = lane * 5;
    int v[5]; int s = 0;
#pragma unroll
    for (int u = 0; u < 5; u++) {
        int idx = base + u;
        v[u] = (idx < nblk) ? d_blocksum[idx] : 0;
        s += v[u];
    }
    int inc = s;
#pragma unroll
    for (int o = 1; o < 32; o <<= 1) {
        int t = __shfl_up_sync(0xffffffffu, inc, o);
        if (lane >= o) inc += t;
    }
    int run = inc - s;
#pragma unroll
    for (int u = 0; u < 5; u++) {
        int idx = base + u;
        if (idx < nblk) d_blocksum[idx] = run;
        run += v[u];
    }
    if (lane == 31) d_rowptr[NN] = inc;
}
__global__ void k_scan3() {
    int i = blockIdx.x * blockDim.x + threadIdx.x;
    if (i < NN) {
        int r = d_rowptr[i] + d_blocksum[i >> 10];
        d_rowptr[i] = r;
        d_cursor[i] = r;
    }
}
// fill CSR (packed edge); weight from degrees inline (deg[r]>=1 guaranteed)
__global__ void k_fill(const int* __restrict__ ei) {
    int e = blockIdx.x * blockDim.x + threadIdx.x;
    if (e < EE) {
        int r = ei[e];
        int c = ei[EE + e];
        int p = atomicAdd(&d_cursor[r], 1);
        int dc = d_deg[c];
        float wr = rsqrtf((float)d_deg[r]);
        float wc = (dc > 0) ? rsqrtf((float)dc) : 0.0f;
        d_edge[p] = make_int2(c, __float_as_int(-wr * wc));
    }
}

// ---------------- weight convert+transpose (hi + residual) ----------------
__global__ void k_wconv(const float* __restrict__ W, int CIN, int COUT,
                        __half* __restrict__ oh, __half* __restrict__ orr) {
    int idx = blockIdx.x * blockDim.x + threadIdx.x;
    int tot = 6 * CIN * COUT;
    if (idx >= tot) return;
    int k = idx / (CIN * COUT);
    int rem = idx - k * (CIN * COUT);
    int c = rem / CIN;
    int j = rem - c * CIN;
    float v = W[(k * CIN + j) * COUT + c];
    __half h = __float2half_rn(v);
    oh[(k * COUT + c) * CIN + j] = h;
    orr[(k * COUT + c) * CIN + j] = __float2half_rn(v - __half2float(h));
}

// ---------------- layer 0: copy x + standard Chebyshev recursion (cin=3, float4 slabs) ----------------
__global__ void k_copy3(const float* __restrict__ x) {
    int n = blockIdx.x * blockDim.x + threadIdx.x;
    if (n >= NN) return;
    float4* A4 = reinterpret_cast<float4*>(d_S + OFF_A4);
    A4[n] = make_float4(x[3 * n], x[3 * n + 1], x[3 * n + 2], 0.0f);
}

__global__ void k_prop3(int si, int sp, int so, float alpha) {
    int n = blockIdx.x * blockDim.x + threadIdx.x;
    if (n >= NN) return;
    int e0 = d_rowptr[n], e1 = d_rowptr[n + 1];
    float4* A4 = reinterpret_cast<float4*>(d_S + OFF_A4);
    const float4* __restrict__ in = A4 + (size_t)si * NN;
    float a0 = 0.f, a1 = 0.f, a2 = 0.f;
    int e = e0;
    for (; e + 4 <= e1; e += 4) {
#pragma unroll
        for (int u = 0; u < 4; u++) {
            int2 ev = d_edge[e + u];
            float v = __int_as_float(ev.y);
            float4 q = __ldg(in + ev.x);
            a0 = fmaf(v, q.x, a0); a1 = fmaf(v, q.y, a1); a2 = fmaf(v, q.z, a2);
        }
    }
    for (; e < e1; ++e) {
        int2 ev = d_edge[e];
        float v = __int_as_float(ev.y);
        float4 q = __ldg(in + ev.x);
        a0 = fmaf(v, q.x, a0); a1 = fmaf(v, q.y, a1); a2 = fmaf(v, q.z, a2);
    }
    float rx = alpha * a0, ry = alpha * a1, rz = alpha * a2;
    if (sp >= 0) {
        float4 pv = A4[(size_t)sp * NN + n];
        rx -= pv.x; ry -= pv.y; rz -= pv.z;
    }
    A4[(size_t)so * NN + n] = make_float4(rx, ry, rz, 0.0f);
}

// ---------------- fused L0 GEMM + GroupNorm + ReLU + fp16-split ----------------
__global__ void __launch_bounds__(256) k_gemm0gn(
    const float* __restrict__ W0, const float* __restrict__ b0,
    const float* __restrict__ g0, const float* __restrict__ be0,
    __half* __restrict__ Hh, __half* __restrict__ Hr)
{
    __shared__ float sW[18 * 128];
    __shared__ float sB[128], sG[128], sBe[128];
    int tid = threadIdx.x;
    for (int i = tid; i < 18 * 128; i += 256) sW[i] = W0[i];
    if (tid < 128) { sB[tid] = b0[tid]; sG[tid] = g0[tid]; sBe[tid] = be0[tid]; }
    __syncthreads();
    int warp = tid >> 5, lane = tid & 31;
    int n = blockIdx.x * 8 + warp;
    const float4* A4 = reinterpret_cast<const float4*>(d_S + OFF_A4);
    float a[18];
#pragma unroll
    for (int k = 0; k < 6; k++) {
        float4 q = A4[(size_t)k * NN + n];
        a[3 * k] = q.x; a[3 * k + 1] = q.y; a[3 * k + 2] = q.z;
    }
    float y[4];
#pragma unroll
    for (int j = 0; j < 4; j++) {
        int c = lane + 32 * j;
        float acc = sB[c];
#pragma unroll
        for (int k = 0; k < 18; k++) acc = fmaf(a[k], sW[k * 128 + c], acc);
        y[j] = acc;
    }
#pragma unroll
    for (int j = 0; j < 4; j++) {
        float s = y[j], q = y[j] * y[j];
#pragma unroll
        for (int o = 1; o < 16; o <<= 1) {
            s += __shfl_xor_sync(0xffffffffu, s, o);
            q += __shfl_xor_sync(0xffffffffu, q, o);
        }
        float mean = s * (1.0f / 16.0f);
        float var = fmaxf(q * (1.0f / 16.0f) - mean * mean, 0.0f);
        float inv = rsqrtf(var + 1e-5f);
        int c = lane + 32 * j;
        float yy = fmaxf(fmaf((y[j] - mean) * inv, sG[c], sBe[c]), 0.0f);
        __half h = __float2half_rn(yy);
        Hh[(size_t)n * 128 + c] = h;
        Hr[(size_t)n * 128 + c] = __float2half_rn(yy - __half2float(h));
    }
}

// ---------------- split-fp16 HMMA GEMM + fused slab-5 half shadow ----------------
template<int KTOT, int BN>
__global__ void __launch_bounds__(256) k_hgemm(const __half* __restrict__ Ah,
                                               const __half* __restrict__ Ar,
                                               const __half* __restrict__ Wh,
                                               const __half* __restrict__ Wr,
                                               int outOff, __half2* __restrict__ outH5) {
    constexpr int NT = BN / 16;
    constexpr int SROW = KTOT + 8;
    constexpr int CP = BN / 2;
    __shared__ __half sBh[BN * SROW];
    __shared__ __half sBr[BN * SROW];
    int tid = threadIdx.x;
    int warp = tid >> 5, lane = tid & 31;
    int g = lane >> 2, t = lane & 3;
    int wm = warp >> 1, wn = warp & 1;
    int rowBase = blockIdx.x * 128;
    int slab = blockIdx.y;

    const __half* whs = Wh + slab * BN * KTOT;
    const __half* wrs = Wr + slab * BN * KTOT;
    for (int i = tid; i < BN * KTOT; i += 256) {
        int r = i / KTOT, c = i - r * KTOT;
        sBh[r * SROW + c] = whs[i];
        sBr[r * SROW + c] = wrs[i];
    }
    __syncthreads();

    float acc[2][NT][4];
#pragma unroll
    for (int mt = 0; mt < 2; mt++)
#pragma unroll
        for (int nt = 0; nt < NT; nt++)
#pragma unroll
            for (int q = 0; q < 4; q++) acc[mt][nt][q] = 0.0f;

    size_t aRow = (size_t)(rowBase + wm * 32 + g) * KTOT;

#pragma unroll
    for (int k16 = 0; k16 < KTOT; k16 += 16) {
        unsigned aH[2][4], aR[2][4];
#pragma unroll
        for (int mt = 0; mt < 2; mt++) {
            size_t base = aRow + (size_t)mt * 16 * KTOT + k16 + 2 * t;
            aH[mt][0] = *reinterpret_cast<const unsigned*>(Ah + base);
            aH[mt][1] = *reinterpret_cast<const unsigned*>(Ah + base + 8 * KTOT);
            aH[mt][2] = *reinterpret_cast<const unsigned*>(Ah + base + 8);
            aH[mt][3] = *reinterpret_cast<const unsigned*>(Ah + base + 8 * KTOT + 8);
            aR[mt][0] = *reinterpret_cast<const unsigned*>(Ar + base);
            aR[mt][1] = *reinterpret_cast<const unsigned*>(Ar + base + 8 * KTOT);
            aR[mt][2] = *reinterpret_cast<const unsigned*>(Ar + base + 8);
            aR[mt][3] = *reinterpret_cast<const unsigned*>(Ar + base + 8 * KTOT + 8);
        }
#pragma unroll
        for (int nt = 0; nt < NT; nt++) {
            int ncol = wn * (BN / 2) + nt * 8 + g;
            const __half* bph = sBh + ncol * SROW + k16 + 2 * t;
            const __half* bpr = sBr + ncol * SROW + k16 + 2 * t;
            unsigned bh0 = *reinterpret_cast<const unsigned*>(bph);
            unsigned bh1 = *reinterpret_cast<const unsigned*>(bph + 8);
            unsigned br0 = *reinterpret_cast<const unsigned*>(bpr);
            unsigned br1 = *reinterpret_cast<const unsigned*>(bpr + 8);
#pragma unroll
            for (int mt = 0; mt < 2; mt++) {
                mma_f16(acc[mt][nt], aH[mt], bh0, bh1);
                mma_f16(acc[mt][nt], aH[mt], br0, br1);
                mma_f16(acc[mt][nt], aR[mt], bh0, bh1);
            }
        }
    }

    const int outStride = 6 * BN;
    bool shadow = (slab == 5) && (outH5 != 0);
#pragma unroll
    for (int mt = 0; mt < 2; mt++) {
        int r0 = rowBase + wm * 32 + mt * 16 + g;
#pragma unroll
        for (int nt = 0; nt < NT; nt++) {
            int colL = wn * (BN / 2) + nt * 8 + 2 * t;
            int col = slab * BN + colL;
            *reinterpret_cast<float2*>(d_S + outOff + (size_t)r0 * outStride + col) =
                make_float2(acc[mt][nt][0], acc[mt][nt][1]);
            *reinterpret_cast<float2*>(d_S + outOff + (size_t)(r0 + 8) * outStride + col) =
                make_float2(acc[mt][nt][2], acc[mt][nt][3]);
            if (shadow) {
                outH5[(size_t)r0 * CP + (colL >> 1)] =
                    __floats2half2_rn(acc[mt][nt][0], acc[mt][nt][1]);
                outH5[(size_t)(r0 + 8) * CP + (colL >> 1)] =
                    __floats2half2_rn(acc[mt][nt][2], acc[mt][nt][3]);
            }
        }
    }
}

// ---------------- Clenshaw gather core (packed edges, half2 gathers) ----------------
template<int CP>
__device__ __forceinline__ void cl_gather(const __half2* __restrict__ inH,
                                          int e0, int e1, int c2,
                                          float& ax, float& ay) {
    int e = e0;
    for (; e + 8 <= e1; e += 8) {
#pragma unroll
        for (int u = 0; u < 8; u++) {
            int2 ev = d_edge[e + u];
            float v = __int_as_float(ev.y);
            float2 gq = __half22float2(inH[ev.x * CP + c2]);
            ax = fmaf(v, gq.x, ax); ay = fmaf(v, gq.y, ay);
        }
    }
    for (; e + 4 <= e1; e += 4) {
#pragma unroll
        for (int u = 0; u < 4; u++) {
            int2 ev = d_edge[e + u];
            float v = __int_as_float(ev.y);
            float2 gq = __half22float2(inH[ev.x * CP + c2]);
            ax = fmaf(v, gq.x, ax); ay = fmaf(v, gq.y, ay);
        }
    }
    for (; e < e1; ++e) {
        int2 ev = d_edge[e];
        float v = __int_as_float(ev.y);
        float2 gq = __half22float2(inH[ev.x * CP + c2]);
        ax = fmaf(v, gq.x, ax); ay = fmaf(v, gq.y, ay);
    }
}

// ---------------- Clenshaw propagation (intermediate, all-fp16 carry) ----------------
// outH[n] = fp16( alpha * (L @ inH)[n] + P[n] - prevH[n] )
// prevH may alias outH (per-row read-before-write; gather never touches outH).
template<int W>
__global__ void __launch_bounds__(128) k_clenshaw(
    const __half2* __restrict__ inH, const __half2* __restrict__ prevH,
    int xOff, int xS, __half2* __restrict__ outH, float alpha)
{
    constexpr int CP = W / 2;
    constexpr int ROWS = 128 / CP;
    int n = blockIdx.x * ROWS + threadIdx.y;
    if (n >= NN) return;
    int c2 = threadIdx.x;
    float ax = 0.0f, ay = 0.0f;
    cl_gather<CP>(inH, d_rowptr[n], d_rowptr[n + 1], c2, ax, ay);

    const float2* x2 = reinterpret_cast<const float2*>(d_S + xOff);
    float2 xv = x2[n * (xS >> 1) + c2];
    float rx = fmaf(alpha, ax, xv.x);
    float ry = fmaf(alpha, ay, xv.y);
    if (prevH) {
        float2 pv = __half22float2(prevH[n * CP + c2]);
        rx -= pv.x; ry -= pv.y;
    }
    outH[n * CP + c2] = __floats2half2_rn(rx, ry);
}

// ---------------- Final Clenshaw step + bias + GroupNorm + ReLU, fused ----------------
template<int W, int F16OUT>
__global__ void __launch_bounds__(128) k_clenshaw_gn(
    const __half2* __restrict__ inH, const __half2* __restrict__ prevH,
    int xOff, int xS,
    const float* __restrict__ bias,
    const float* __restrict__ gamma, const float* __restrict__ beta,
    __half* __restrict__ Hh, __half* __restrict__ Hr, int f32Off)
{
    constexpr int CP = W / 2;
    constexpr int ROWS = 128 / CP;
    constexpr int GS = W / 8;
    constexpr int LGL = GS / 2;
    int n = blockIdx.x * ROWS + threadIdx.y;
    if (n >= NN) return;
    int c2 = threadIdx.x;
    float ax = 0.0f, ay = 0.0f;
    cl_gather<CP>(inH, d_rowptr[n], d_rowptr[n + 1], c2, ax, ay);

    const float2* x2 = reinterpret_cast<const float2*>(d_S + xOff);
    float2 xv = x2[n * (xS >> 1) + c2];
    float2 pv = __half22float2(prevH[n * CP + c2]);
    float rx = ax + xv.x - pv.x + bias[2 * c2];
    float ry = ay + xv.y - pv.y + bias[2 * c2 + 1];

    float s = rx + ry;
    float q = rx * rx + ry * ry;
#pragma unroll
    for (int o = 1; o < LGL; o <<= 1) {
        s += __shfl_xor_sync(0xffffffffu, s, o);
        q += __shfl_xor_sync(0xffffffffu, q, o);
    }
    float mean = s * (1.0f / GS);
    float var = fmaxf(q * (1.0f / GS) - mean * mean, 0.0f);
    float inv = rsqrtf(var + 1e-5f);
    float y0 = fmaxf(fmaf((rx - mean) * inv, gamma[2 * c2],     beta[2 * c2]),     0.0f);
    float y1 = fmaxf(fmaf((ry - mean) * inv, gamma[2 * c2 + 1], beta[2 * c2 + 1]), 0.0f);

    if (F16OUT) {
        __half h0 = __float2half_rn(y0), h1 = __float2half_rn(y1);
        *reinterpret_cast<__half2*>(Hh + (size_t)n * W + 2 * c2) =
            __halves2half2(h0, h1);
        *reinterpret_cast<__half2*>(Hr + (size_t)n * W + 2 * c2) =
            __floats2half2_rn(y0 - __half2float(h0), y1 - __half2float(h1));
    } else {
        float2* o2 = reinterpret_cast<float2*>(d_S + f32Off);
        o2[n * CP + c2] = make_float2(y0, y1);
    }
}

// ---------------- final projection: [16,320000] @ [320000,128], split-K ----------------
__global__ void __launch_bounds__(128) k_final(const float* __restrict__ Wl) {
    const int CHUNK = 320;
    int blk = blockIdx.x;
    int t = threadIdx.x;
    int j0base = blk * CHUNK;
    float acc[BB];
#pragma unroll
    for (int b = 0; b < BB; b++) acc[b] = 0.0f;
    __shared__ float Hs[BB][32];
    for (int jt = 0; jt < CHUNK; jt += 32) {
        int j0 = j0base + jt;
        for (int i = t; i < BB * 32; i += 128) {
            int b = i >> 5, jj = i & 31;
            Hs[b][jj] = d_S[OFF_H3 + b * 320000 + j0 + jj];
        }
        __syncthreads();
#pragma unroll
        for (int jj = 0; jj < 32; jj++) {
            float w = Wl[(j0 + jj) * 128 + t];
#pragma unroll
            for (int b = 0; b < BB; b++)
                acc[b] = fmaf(Hs[b][jj], w, acc[b]);
        }
        __syncthreads();
    }
#pragma unroll
    for (int b = 0; b < BB; b++)
        d_part[blk * 2048 + b * 128 + t] = acc[b];
}

__global__ void k_reduce(const float* __restrict__ bl, float* __restrict__ out) {
    int o = blockIdx.x;
    int t = threadIdx.x;
    float s = 0.0f;
    for (int p = t; p < 1000; p += 32) s += d_part[p * 2048 + o];
#pragma unroll
    for (int off = 16; off; off >>= 1)
        s += __shfl_down_sync(0xffffffffu, s, off);
    if (t == 0) out[o] = s + bl[o & 127];
}

// ---------------- launch ----------------
extern "C" void kernel_launch(void* const* d_in, const int* in_sizes, int n_in,
                              void* d_out, int out_size) {
    const float* x  = (const float*)d_in[0];
    const int*   ei = (const int*)d_in[1];          // int32 (JAX x64 disabled)
    const float* W0 = (const float*)d_in[2];
    const float* b0 = (const float*)d_in[3];
    const float* g0 = (const float*)d_in[4];
    const float* be0 = (const float*)d_in[5];
    const float* W1 = (const float*)d_in[6];
    const float* b1 = (const float*)d_in[7];
    const float* g1 = (const float*)d_in[8];
    const float* be1 = (const float*)d_in[9];
    const float* W2 = (const float*)d_in[10];
    const float* b2 = (const float*)d_in[11];
    const float* g2 = (const float*)d_in[12];
    const float* be2 = (const float*)d_in[13];
    const float* Wl = (const float*)d_in[14];
    const float* bl = (const float*)d_in[15];
    float* out = (float*)d_out;

    __half *Hh, *Hr, *Wth, *Wtr;
    __half2 *H0, *H1;
    cudaGetSymbolAddress((void**)&Hh, d_Hh);
    cudaGetSymbolAddress((void**)&Hr, d_Hr);
    cudaGetSymbolAddress((void**)&Wth, d_Wth);
    cudaGetSymbolAddress((void**)&Wtr, d_Wtr);
    cudaGetSymbolAddress((void**)&H0, d_Bh0);
    cudaGetSymbolAddress((void**)&H1, d_Bh1);

    // --- preprocessing (wconv early so ncu's idx-3 slot = k_deg) ---
    k_zero_deg<<<cdiv(NN, 256), 256>>>();
    k_wconv<<<cdiv(6 * 128 * 64, 256), 256>>>(W1, 128, 64, Wth, Wtr);
    k_wconv<<<cdiv(6 * 64 * 32, 256), 256>>>(W2, 64, 32, Wth + WT2_OFF, Wtr + WT2_OFF);
    k_deg<<<cdiv(EE, 256), 256>>>(ei);
    int nblk = cdiv(NN, 1024);
    k_scan1<<<nblk, 1024>>>();
    k_scan2<<<1, 32>>>(nblk);
    k_scan3<<<cdiv(NN, 256), 256>>>();
    k_fill<<<cdiv(EE, 256), 256>>>(ei);

    // --- layer 0: standard recursion (cin=3 -> cout=128), fused GEMM+GN ---
    k_copy3<<<cdiv(NN, 256), 256>>>(x);
    k_prop3<<<cdiv(NN, 128), 128>>>(0, -1, 1, 1.0f);
    k_prop3<<<cdiv(NN, 128), 128>>>(1, 0, 2, 2.0f);
    k_prop3<<<cdiv(NN, 128), 128>>>(2, 1, 3, 2.0f);
    k_prop3<<<cdiv(NN, 128), 128>>>(3, 2, 4, 2.0f);
    k_prop3<<<cdiv(NN, 128), 128>>>(4, 3, 5, 2.0f);
    k_gemm0gn<<<NN / 8, 256>>>(W0, b0, g0, be0, Hh, Hr);

    // --- layer 1 (cin=128 -> cout=64): HMMA, fp16-carry Clenshaw, fused GN ---
    k_hgemm<128, 64><<<dim3(NN / 128, 6), 256>>>(Hh, Hr, Wth, Wtr, OFF_P, H0);
    {
        const int P5 = OFF_P + 5 * 64, P4 = OFF_P + 4 * 64, P3 = OFF_P + 3 * 64;
        const int P2 = OFF_P + 2 * 64, P1 = OFF_P + 1 * 64, P0 = OFF_P;
        dim3 blk(32, 4); int g = NN / 4;
        // b5 = H0 (hgemm shadow)
        k_clenshaw<64><<<g, blk>>>(H0, (const __half2*)0, P4, 384, H1, 2.0f);  // b4
        k_clenshaw<64><<<g, blk>>>(H1, H0, P3, 384, H0, 2.0f);                 // b3 (prev b5, in-place)
        k_clenshaw<64><<<g, blk>>>(H0, H1, P2, 384, H1, 2.0f);                 // b2 (prev b4)
        k_clenshaw<64><<<g, blk>>>(H1, H0, P1, 384, H0, 2.0f);                 // b1 (prev b3)
        k_clenshaw_gn<64, 1><<<g, blk>>>(H0, H1, P0, 384, b1, g1, be1, Hh, Hr, 0);
    }

    // --- layer 2 (cin=64 -> cout=32): HMMA, fp16-carry Clenshaw, fused GN ---
    k_hgemm<64, 32><<<dim3(NN / 128, 6), 256>>>(Hh, Hr, Wth + WT2_OFF, Wtr + WT2_OFF, OFF_P, H0);
    {
        const int P5 = OFF_P + 5 * 32, P4 = OFF_P + 4 * 32, P3 = OFF_P + 3 * 32;
        const int P2 = OFF_P + 2 * 32, P1 = OFF_P + 1 * 32, P0 = OFF_P;
        dim3 blk(16, 8); int g = NN / 8;
        k_clenshaw<32><<<g, blk>>>(H0, (const __half2*)0, P4, 192, H1, 2.0f);
        k_clenshaw<32><<<g, blk>>>(H1, H0, P3, 192, H0, 2.0f);
        k_clenshaw<32><<<g, blk>>>(H0, H1, P2, 192, H1, 2.0f);
        k_clenshaw<32><<<g, blk>>>(H1, H0, P1, 192, H0, 2.0f);
        k_clenshaw_gn<32, 0><<<g, blk>>>(H0, H1, P0, 192, b2, g2, be2,
                                         (__half*)0, (__half*)0, OFF_H3);
    }

    // --- final projection ---
    k_final<<<1000, 128>>>(Wl);
    k_reduce<<<2048, 32>>>(bl, out);
}